// round 4
// baseline (speedup 1.0000x reference)
#include <cuda_runtime.h>
#include <cuda_bf16.h>
#include <cstdint>

#define T_TOK 4096
#define H_DIM 1024
#define I_DIM 1024
#define E_NUM 8
#define S_SLOTS (T_TOK * 2)
#define BM 128
#define MAX_TILES (S_SLOTS / BM + E_NUM)   // 72

// ---------------- device scratch (allocation-free rule) ----------------
__device__ int   d_counts[E_NUM];
__device__ int   d_expert_of_slot[S_SLOTS];
__device__ float d_w_of_slot[S_SLOTS];
__device__ int   d_perm[S_SLOTS];
__device__ int   d_tile_expert[MAX_TILES];
__device__ int   d_tile_row0[MAX_TILES];
__device__ int   d_tile_rowend[MAX_TILES];
__device__ int   d_num_tiles;

__device__ __align__(16) __nv_bfloat16 d_x_h[(size_t)T_TOK * H_DIM];
__device__ __align__(16) __nv_bfloat16 d_x_l[(size_t)T_TOK * H_DIM];
__device__ __align__(16) __nv_bfloat16 d_upwT_h[(size_t)E_NUM * 2 * I_DIM * H_DIM]; // [e][n][k]
__device__ __align__(16) __nv_bfloat16 d_upwT_l[(size_t)E_NUM * 2 * I_DIM * H_DIM];
__device__ __align__(16) __nv_bfloat16 d_dnwT_h[(size_t)E_NUM * H_DIM * I_DIM];     // [e][n][k]
__device__ __align__(16) __nv_bfloat16 d_dnwT_l[(size_t)E_NUM * H_DIM * I_DIM];
__device__ __align__(16) __nv_bfloat16 d_hbuf_h[(size_t)S_SLOTS * I_DIM];
__device__ __align__(16) __nv_bfloat16 d_hbuf_l[(size_t)S_SLOTS * I_DIM];
__device__ __align__(16) float d_acc[(size_t)S_SLOTS * H_DIM];                      // 32 MB

// ---------------- PTX helpers ----------------
__device__ __forceinline__ uint32_t smem_u32(const void* p) {
    uint32_t a;
    asm("{ .reg .u64 t; cvta.to.shared.u64 t, %1; cvt.u32.u64 %0, t; }" : "=r"(a) : "l"(p));
    return a;
}
#define CP_ASYNC16(sm, gp, sz) \
    asm volatile("cp.async.cg.shared.global [%0], [%1], 16, %2;" :: "r"(sm), "l"(gp), "r"(sz) : "memory")
#define CP_COMMIT() asm volatile("cp.async.commit_group;" ::: "memory")
#define CP_WAIT1()  asm volatile("cp.async.wait_group 1;" ::: "memory")
#define CP_WAIT0()  asm volatile("cp.async.wait_group 0;" ::: "memory")
#define LDSM_X4(r0, r1, r2, r3, addr) \
    asm volatile("ldmatrix.sync.aligned.m8n8.x4.shared.b16 {%0,%1,%2,%3}, [%4];" \
        : "=r"(r0), "=r"(r1), "=r"(r2), "=r"(r3) : "r"(addr))

__device__ __forceinline__ void mma_bf16(float* d, const uint32_t* a, uint32_t b0, uint32_t b1) {
    asm volatile("mma.sync.aligned.m16n8k16.row.col.f32.bf16.bf16.f32 "
        "{%0,%1,%2,%3}, {%4,%5,%6,%7}, {%8,%9}, {%0,%1,%2,%3};"
        : "+f"(d[0]), "+f"(d[1]), "+f"(d[2]), "+f"(d[3])
        : "r"(a[0]), "r"(a[1]), "r"(a[2]), "r"(a[3]), "r"(b0), "r"(b1));
}

__device__ __forceinline__ uint32_t packbf(float a, float b) {  // a->lo, b->hi
    uint32_t r;
    asm("cvt.rn.bf16x2.f32 %0, %1, %2;" : "=r"(r) : "f"(b), "f"(a));
    return r;
}
__device__ __forceinline__ float bf16r(float v) {
    return __bfloat162float(__float2bfloat16(v));
}

// ---------------- router + sort ----------------
__global__ void zero_counts_kernel() {
    if (threadIdx.x < E_NUM) d_counts[threadIdx.x] = 0;
}
__global__ void router_kernel(const float* __restrict__ logits) {
    int t = blockIdx.x * blockDim.x + threadIdx.x;
    if (t >= T_TOK) return;
    float l[E_NUM];
#pragma unroll
    for (int e = 0; e < E_NUM; e++) l[e] = logits[t * E_NUM + e];
    int i0 = 0;
#pragma unroll
    for (int e = 1; e < E_NUM; e++) if (l[e] > l[i0]) i0 = e;
    int i1 = (i0 == 0) ? 1 : 0;
#pragma unroll
    for (int e = 0; e < E_NUM; e++) {
        if (e == i0 || e == i1) continue;
        if (l[e] > l[i1]) i1 = e;
    }
    float w0 = 1.f / (1.f + expf(l[i1] - l[i0]));
    d_expert_of_slot[2 * t] = i0; d_expert_of_slot[2 * t + 1] = i1;
    d_w_of_slot[2 * t] = w0;      d_w_of_slot[2 * t + 1] = 1.f - w0;
    atomicAdd(&d_counts[i0], 1);
    atomicAdd(&d_counts[i1], 1);
}
__global__ void setup_kernel() {
    __shared__ int s_off[E_NUM];
    __shared__ int s_cur[E_NUM];
    if (threadIdx.x == 0) {
        int acc = 0, nt = 0;
        for (int e = 0; e < E_NUM; e++) {
            int c = d_counts[e];
            s_off[e] = acc;
            for (int r = 0; r < c; r += BM) {
                d_tile_expert[nt] = e;
                d_tile_row0[nt] = acc + r;
                d_tile_rowend[nt] = acc + c;
                nt++;
            }
            acc += c;
        }
        d_num_tiles = nt;
    }
    if (threadIdx.x < E_NUM) s_cur[threadIdx.x] = 0;
    __syncthreads();
    for (int s = threadIdx.x; s < S_SLOTS; s += blockDim.x) {
        int e = d_expert_of_slot[s];
        int pos = s_off[e] + atomicAdd(&s_cur[e], 1);
        d_perm[pos] = s;
    }
}

// ---------------- prepass: x -> bf16 hi/lo ----------------
__global__ void conv_x_kernel(const float* __restrict__ x) {
    int i = blockIdx.x * blockDim.x + threadIdx.x;
    float4 v = ((const float4*)x)[i];
    uint32_t* oh = (uint32_t*)d_x_h;
    uint32_t* ol = (uint32_t*)d_x_l;
    oh[2 * i]     = packbf(v.x, v.y);
    oh[2 * i + 1] = packbf(v.z, v.w);
    ol[2 * i]     = packbf(v.x - bf16r(v.x), v.y - bf16r(v.y));
    ol[2 * i + 1] = packbf(v.z - bf16r(v.z), v.w - bf16r(v.w));
}

// ---------------- prepass: W[e][K][N] -> Wt[e][N][K] bf16 hi/lo ----------------
template <int WSEL>   // 0 = up_weight, 1 = down_weight
__global__ void conv_wT_kernel(const float* __restrict__ W, int K, int N) {
    __shared__ float tf[32][33];
    __nv_bfloat16* Wh = (WSEL == 0) ? d_upwT_h : d_dnwT_h;
    __nv_bfloat16* Wl = (WSEL == 0) ? d_upwT_l : d_dnwT_l;
    const float* Wm = W + (size_t)blockIdx.z * K * N;
    int n0 = blockIdx.x * 32, k0 = blockIdx.y * 32;
    int tx = threadIdx.x, ty = threadIdx.y;
#pragma unroll
    for (int j = 0; j < 4; j++)
        tf[ty + 8 * j][tx] = Wm[(size_t)(k0 + ty + 8 * j) * N + n0 + tx];
    __syncthreads();
    int pid = tx & 15, half = tx >> 4;
    size_t obase = (size_t)blockIdx.z * N * K;
#pragma unroll
    for (int j = 0; j < 4; j++) {
        int nl = ty + 8 * j;
        float v0 = tf[2 * pid][nl], v1 = tf[2 * pid + 1][nl];
        if (half == 0) {
            uint32_t* dst = (uint32_t*)(Wh + obase + (size_t)(n0 + nl) * K + k0);
            dst[pid] = packbf(v0, v1);
        } else {
            uint32_t* dst = (uint32_t*)(Wl + obase + (size_t)(n0 + nl) * K + k0);
            dst[pid] = packbf(v0 - bf16r(v0), v1 - bf16r(v1));
        }
    }
}

// ---------------- HMMA grouped GEMM ----------------
// smem: 3 stages x 4 planes (Ah,Al,Bh,Bl) x 128 rows x 80B(64 data+16 pad) = 122880 B
#define PLANE_B 10240
#define STAGE_B 40960
#define N_STAGE 3
#define SMEM_B  (N_STAGE * STAGE_B)

template <int G>   // 1 = gate/up + SiLU, 2 = down + weight scatter
__global__ void __launch_bounds__(256, 1) gemm_hmma_kernel() {
    int tile = blockIdx.y;
    if (tile >= d_num_tiles) return;
    const int e = d_tile_expert[tile];
    const int row0 = d_tile_row0[tile];
    const int rowend = d_tile_rowend[tile];
    const int nb = blockIdx.x;

    extern __shared__ char smem[];
    const uint32_t sb = smem_u32(smem);
    const int tid = threadIdx.x, wid = tid >> 5, lane = tid & 31;

    // ---- fill mapping: plane = tid>>6 (Ah,Al,Bh,Bl); rows f and f+64 ----
    const int plane = tid >> 6, f = tid & 63;
    const __nv_bfloat16* p0 = d_x_h;
    const __nv_bfloat16* p1 = d_x_h;
    int z0 = 16, z1 = 16;
    if (plane < 2) {
        const __nv_bfloat16* bp = (G == 1) ? (plane ? d_x_l : d_x_h)
                                           : (plane ? d_hbuf_l : d_hbuf_h);
        int g0 = row0 + f, g1 = row0 + f + 64;
        if (g0 < rowend) p0 = bp + (size_t)(G == 1 ? (d_perm[g0] >> 1) : g0) * 1024; else z0 = 0;
        if (g1 < rowend) p1 = bp + (size_t)(G == 1 ? (d_perm[g1] >> 1) : g1) * 1024; else z1 = 0;
    } else {
        if (G == 1) {
            // interleave gate/up: block col n -> unit nb*64+(n>>1); odd n = up
            const __nv_bfloat16* bp = ((plane == 3) ? d_upwT_l : d_upwT_h)
                                      + (size_t)e * 2 * I_DIM * H_DIM;
            int u0 = nb * 64 + (f >> 1), u1 = u0 + 32;
            p0 = bp + (size_t)((f & 1) ? I_DIM + u0 : u0) * 1024;
            p1 = bp + (size_t)((f & 1) ? I_DIM + u1 : u1) * 1024;
        } else {
            const __nv_bfloat16* bp = ((plane == 3) ? d_dnwT_l : d_dnwT_h)
                                      + (size_t)e * H_DIM * I_DIM;
            p0 = bp + (size_t)(nb * 128 + f) * 1024;
            p1 = bp + (size_t)(nb * 128 + f + 64) * 1024;
        }
    }
    const uint32_t dst0 = sb + plane * PLANE_B + f * 80;
    const uint32_t dst1 = dst0 + 64 * 80;

    // ---- warp tiling: 4 m-warps x 2 n-warps; warp tile 32x64 ----
    const int warp_m = wid >> 1, warp_n = wid & 1;
    const uint32_t a_off = (uint32_t)((warp_m * 32 + (lane & 15)) * 80 + (lane >> 4) * 16);
    const uint32_t b_off = (uint32_t)((warp_n * 64 + ((lane >> 4) & 1) * 8 + (lane & 7)) * 80
                                      + ((lane >> 3) & 1) * 16);

    float acc[2][8][4];
#pragma unroll
    for (int mt = 0; mt < 2; mt++)
#pragma unroll
        for (int nt = 0; nt < 8; nt++)
#pragma unroll
            for (int q = 0; q < 4; q++) acc[mt][nt][q] = 0.f;

    auto fill = [&](int stage, int c) {
        uint32_t s0 = dst0 + stage * STAGE_B;
        uint32_t s1 = dst1 + stage * STAGE_B;
        const char* g0 = (const char*)p0 + c * 64;
        const char* g1 = (const char*)p1 + c * 64;
#pragma unroll
        for (int s = 0; s < 4; s++) CP_ASYNC16(s0 + s * 16, g0 + s * 16, z0);
#pragma unroll
        for (int s = 0; s < 4; s++) CP_ASYNC16(s1 + s * 16, g1 + s * 16, z1);
    };

    fill(0, 0); CP_COMMIT();
    fill(1, 1); CP_COMMIT();

    for (int c = 0; c < 32; c++) {
        if (c == 31) { CP_WAIT0(); } else { CP_WAIT1(); }
        __syncthreads();
        if (c + 2 < 32) { fill((c + 2) % N_STAGE, c + 2); CP_COMMIT(); }
        const uint32_t st = sb + (c % N_STAGE) * STAGE_B;
#pragma unroll
        for (int kb = 0; kb < 64; kb += 32) {
            uint32_t ah[2][4], al[2][4], bh[4][4], bl[4][4];
#pragma unroll
            for (int mt = 0; mt < 2; mt++) {
                uint32_t aa = st + a_off + mt * 1280 + kb;
                LDSM_X4(ah[mt][0], ah[mt][1], ah[mt][2], ah[mt][3], aa);
                LDSM_X4(al[mt][0], al[mt][1], al[mt][2], al[mt][3], aa + PLANE_B);
            }
#pragma unroll
            for (int bp2 = 0; bp2 < 4; bp2++) {
                uint32_t ba = st + 2 * PLANE_B + b_off + bp2 * 1280 + kb;
                LDSM_X4(bh[bp2][0], bh[bp2][1], bh[bp2][2], bh[bp2][3], ba);
                LDSM_X4(bl[bp2][0], bl[bp2][1], bl[bp2][2], bl[bp2][3], ba + PLANE_B);
            }
            // ---- term-major: dependent MMAs on the same acc are 16 apart ----
#pragma unroll
            for (int mt = 0; mt < 2; mt++)
#pragma unroll
                for (int nt = 0; nt < 8; nt++)
                    mma_bf16(acc[mt][nt], ah[mt],
                             bh[nt >> 1][(nt & 1) * 2], bh[nt >> 1][(nt & 1) * 2 + 1]);
#pragma unroll
            for (int mt = 0; mt < 2; mt++)
#pragma unroll
                for (int nt = 0; nt < 8; nt++)
                    mma_bf16(acc[mt][nt], al[mt],
                             bh[nt >> 1][(nt & 1) * 2], bh[nt >> 1][(nt & 1) * 2 + 1]);
#pragma unroll
            for (int mt = 0; mt < 2; mt++)
#pragma unroll
                for (int nt = 0; nt < 8; nt++)
                    mma_bf16(acc[mt][nt], ah[mt],
                             bl[nt >> 1][(nt & 1) * 2], bl[nt >> 1][(nt & 1) * 2 + 1]);
        }
        __syncthreads();
    }

    // ---- epilogue ----
    if (G == 1) {
#pragma unroll
        for (int mt = 0; mt < 2; mt++) {
            int rA = row0 + warp_m * 32 + mt * 16 + (lane >> 2);
            int rB = rA + 8;
#pragma unroll
            for (int nt = 0; nt < 8; nt++) {
                int col = nb * 64 + warp_n * 32 + nt * 4 + (lane & 3);
                float* d = acc[mt][nt];
                if (rA < rowend) {
                    float g = d[0], u = d[1];
                    float h = g / (1.f + expf(-g)) * u;
                    d_hbuf_h[(size_t)rA * 1024 + col] = __float2bfloat16(h);
                    d_hbuf_l[(size_t)rA * 1024 + col] = __float2bfloat16(h - bf16r(h));
                }
                if (rB < rowend) {
                    float g = d[2], u = d[3];
                    float h = g / (1.f + expf(-g)) * u;
                    d_hbuf_h[(size_t)rB * 1024 + col] = __float2bfloat16(h);
                    d_hbuf_l[(size_t)rB * 1024 + col] = __float2bfloat16(h - bf16r(h));
                }
            }
        }
    } else {
#pragma unroll
        for (int mt = 0; mt < 2; mt++) {
            int rA = row0 + warp_m * 32 + mt * 16 + (lane >> 2);
            int rB = rA + 8;
            if (rA < rowend) {
                int slot = d_perm[rA];
                float w = d_w_of_slot[slot];
                float* po = &d_acc[(size_t)slot * 1024 + nb * 128 + warp_n * 64 + 2 * (lane & 3)];
#pragma unroll
                for (int nt = 0; nt < 8; nt++) {
                    float* d = acc[mt][nt];
                    *(float2*)(po + nt * 8) = make_float2(w * d[0], w * d[1]);
                }
            }
            if (rB < rowend) {
                int slot = d_perm[rB];
                float w = d_w_of_slot[slot];
                float* po = &d_acc[(size_t)slot * 1024 + nb * 128 + warp_n * 64 + 2 * (lane & 3)];
#pragma unroll
                for (int nt = 0; nt < 8; nt++) {
                    float* d = acc[mt][nt];
                    *(float2*)(po + nt * 8) = make_float2(w * d[2], w * d[3]);
                }
            }
        }
    }
}

// ---------------- combine: out[t] = acc[2t] + acc[2t+1] ----------------
__global__ void combine_kernel(float* __restrict__ out) {
    int i = blockIdx.x * blockDim.x + threadIdx.x;
    int t = i / (H_DIM / 4);
    int c = i % (H_DIM / 4);
    const float4* a0 = (const float4*)&d_acc[(size_t)(2 * t) * H_DIM];
    const float4* a1 = (const float4*)&d_acc[(size_t)(2 * t + 1) * H_DIM];
    float4 x0 = a0[c], x1 = a1[c];
    ((float4*)out)[i] = make_float4(x0.x + x1.x, x0.y + x1.y, x0.z + x1.z, x0.w + x1.w);
}

// ---------------- launch ----------------
extern "C" void kernel_launch(void* const* d_in, const int* in_sizes, int n_in,
                              void* d_out, int out_size) {
    (void)in_sizes; (void)n_in; (void)out_size;
    const float* x      = (const float*)d_in[0];
    const float* logits = (const float*)d_in[1];
    const float* up_w   = (const float*)d_in[2];
    const float* down_w = (const float*)d_in[3];
    float* out = (float*)d_out;

    cudaFuncSetAttribute(gemm_hmma_kernel<1>, cudaFuncAttributeMaxDynamicSharedMemorySize, SMEM_B);
    cudaFuncSetAttribute(gemm_hmma_kernel<2>, cudaFuncAttributeMaxDynamicSharedMemorySize, SMEM_B);

    zero_counts_kernel<<<1, 32>>>();
    router_kernel<<<T_TOK / 256, 256>>>(logits);
    setup_kernel<<<1, 256>>>();
    conv_x_kernel<<<T_TOK * H_DIM / 4 / 256, 256>>>(x);
    conv_wT_kernel<0><<<dim3(2 * I_DIM / 32, H_DIM / 32, E_NUM), dim3(32, 8)>>>(up_w, H_DIM, 2 * I_DIM);
    conv_wT_kernel<1><<<dim3(H_DIM / 32, I_DIM / 32, E_NUM), dim3(32, 8)>>>(down_w, I_DIM, H_DIM);
    gemm_hmma_kernel<1><<<dim3(16, MAX_TILES), 256, SMEM_B>>>();
    gemm_hmma_kernel<2><<<dim3(8, MAX_TILES), 256, SMEM_B>>>();
    combine_kernel<<<T_TOK * H_DIM / 4 / 256, 256>>>(out);
}

// round 5
// speedup vs baseline: 1.0044x; 1.0044x over previous
#include <cuda_runtime.h>
#include <cuda_bf16.h>
#include <cstdint>

#define T_TOK 4096
#define H_DIM 1024
#define I_DIM 1024
#define E_NUM 8
#define S_SLOTS (T_TOK * 2)
#define BM 128
#define MAX_TILES (S_SLOTS / BM + E_NUM)   // 72

// ---------------- device scratch ----------------
__device__ int   d_counts[E_NUM];
__device__ int   d_expert_of_slot[S_SLOTS];
__device__ float d_w_of_slot[S_SLOTS];
__device__ int   d_perm[S_SLOTS];
__device__ int   d_tile_expert[MAX_TILES];
__device__ int   d_tile_row0[MAX_TILES];
__device__ int   d_tile_rowend[MAX_TILES];
__device__ int   d_num_tiles;

__device__ __align__(16) __nv_bfloat16 d_x_h[(size_t)T_TOK * H_DIM];
__device__ __align__(16) __nv_bfloat16 d_x_l[(size_t)T_TOK * H_DIM];
__device__ __align__(16) __nv_bfloat16 d_upwT_h[(size_t)E_NUM * 2 * I_DIM * H_DIM]; // [e][n][k]
__device__ __align__(16) __nv_bfloat16 d_upwT_l[(size_t)E_NUM * 2 * I_DIM * H_DIM];
__device__ __align__(16) __nv_bfloat16 d_dnwT_h[(size_t)E_NUM * H_DIM * I_DIM];     // [e][n][k]
__device__ __align__(16) __nv_bfloat16 d_dnwT_l[(size_t)E_NUM * H_DIM * I_DIM];
__device__ __align__(16) __nv_bfloat16 d_hbuf_h[(size_t)S_SLOTS * I_DIM];
__device__ __align__(16) __nv_bfloat16 d_hbuf_l[(size_t)S_SLOTS * I_DIM];
__device__ __align__(16) float d_acc[(size_t)S_SLOTS * H_DIM];

// ---------------- PTX helpers ----------------
__device__ __forceinline__ uint32_t smem_u32(const void* p) {
    uint32_t a;
    asm("{ .reg .u64 t; cvta.to.shared.u64 t, %1; cvt.u32.u64 %0, t; }" : "=r"(a) : "l"(p));
    return a;
}
#define CP_ASYNC16(sm, gp, sz) \
    asm volatile("cp.async.cg.shared.global [%0], [%1], 16, %2;" :: "r"(sm), "l"(gp), "r"(sz) : "memory")
#define CP_COMMIT() asm volatile("cp.async.commit_group;" ::: "memory")
#define CP_WAIT1()  asm volatile("cp.async.wait_group 1;" ::: "memory")
#define CP_WAIT0()  asm volatile("cp.async.wait_group 0;" ::: "memory")
#define LDSM_X4(r0, r1, r2, r3, addr) \
    asm volatile("ldmatrix.sync.aligned.m8n8.x4.shared.b16 {%0,%1,%2,%3}, [%4];" \
        : "=r"(r0), "=r"(r1), "=r"(r2), "=r"(r3) : "r"(addr))

__device__ __forceinline__ void mma_bf16(float* d, const uint32_t* a, uint32_t b0, uint32_t b1) {
    asm volatile("mma.sync.aligned.m16n8k16.row.col.f32.bf16.bf16.f32 "
        "{%0,%1,%2,%3}, {%4,%5,%6,%7}, {%8,%9}, {%0,%1,%2,%3};"
        : "+f"(d[0]), "+f"(d[1]), "+f"(d[2]), "+f"(d[3])
        : "r"(a[0]), "r"(a[1]), "r"(a[2]), "r"(a[3]), "r"(b0), "r"(b1));
}

__device__ __forceinline__ uint32_t packbf(float a, float b) {  // a->lo, b->hi
    uint32_t r;
    asm("cvt.rn.bf16x2.f32 %0, %1, %2;" : "=r"(r) : "f"(b), "f"(a));
    return r;
}
__device__ __forceinline__ float bf16r(float v) {
    return __bfloat162float(__float2bfloat16(v));
}

// ---------------- conv_x (also zeroes expert counts; launched FIRST) ----------
__global__ void conv_x_kernel(const float* __restrict__ x) {
    if (blockIdx.x == 0 && threadIdx.x < E_NUM) d_counts[threadIdx.x] = 0;
    int i = blockIdx.x * blockDim.x + threadIdx.x;
    float4 v = ((const float4*)x)[i];
    uint32_t* oh = (uint32_t*)d_x_h;
    uint32_t* ol = (uint32_t*)d_x_l;
    oh[2 * i]     = packbf(v.x, v.y);
    oh[2 * i + 1] = packbf(v.z, v.w);
    ol[2 * i]     = packbf(v.x - bf16r(v.x), v.y - bf16r(v.y));
    ol[2 * i + 1] = packbf(v.z - bf16r(v.z), v.w - bf16r(v.w));
}

// ---------------- router + sort ----------------
__global__ void router_kernel(const float* __restrict__ logits) {
    int t = blockIdx.x * blockDim.x + threadIdx.x;
    if (t >= T_TOK) return;
    float l[E_NUM];
#pragma unroll
    for (int e = 0; e < E_NUM; e++) l[e] = logits[t * E_NUM + e];
    int i0 = 0;
#pragma unroll
    for (int e = 1; e < E_NUM; e++) if (l[e] > l[i0]) i0 = e;
    int i1 = (i0 == 0) ? 1 : 0;
#pragma unroll
    for (int e = 0; e < E_NUM; e++) {
        if (e == i0 || e == i1) continue;
        if (l[e] > l[i1]) i1 = e;
    }
    float w0 = 1.f / (1.f + expf(l[i1] - l[i0]));
    d_expert_of_slot[2 * t] = i0; d_expert_of_slot[2 * t + 1] = i1;
    d_w_of_slot[2 * t] = w0;      d_w_of_slot[2 * t + 1] = 1.f - w0;
    atomicAdd(&d_counts[i0], 1);
    atomicAdd(&d_counts[i1], 1);
}
__global__ void setup_kernel() {
    __shared__ int s_off[E_NUM];
    __shared__ int s_cur[E_NUM];
    if (threadIdx.x == 0) {
        int acc = 0, nt = 0;
        for (int e = 0; e < E_NUM; e++) {
            int c = d_counts[e];
            s_off[e] = acc;
            for (int r = 0; r < c; r += BM) {
                d_tile_expert[nt] = e;
                d_tile_row0[nt] = acc + r;
                d_tile_rowend[nt] = acc + c;
                nt++;
            }
            acc += c;
        }
        d_num_tiles = nt;
    }
    if (threadIdx.x < E_NUM) s_cur[threadIdx.x] = 0;
    __syncthreads();
    for (int s = threadIdx.x; s < S_SLOTS; s += blockDim.x) {
        int e = d_expert_of_slot[s];
        int pos = s_off[e] + atomicAdd(&s_cur[e], 1);
        d_perm[pos] = s;
    }
}

// ---------------- merged weight transpose+convert (up z<8, down z>=8) --------
__global__ void conv_w_kernel(const float* __restrict__ up_w,
                              const float* __restrict__ dn_w) {
    __shared__ float tf[32][33];
    int z = blockIdx.z;
    const float* Wm;
    __nv_bfloat16 *Wh, *Wl;
    int K = 1024, N;
    if (z < E_NUM) {
        N = 2048;
        Wm = up_w + (size_t)z * K * N;
        Wh = d_upwT_h + (size_t)z * N * K;
        Wl = d_upwT_l + (size_t)z * N * K;
    } else {
        N = 1024;
        if (blockIdx.x >= 32) return;
        int e = z - E_NUM;
        Wm = dn_w + (size_t)e * K * N;
        Wh = d_dnwT_h + (size_t)e * N * K;
        Wl = d_dnwT_l + (size_t)e * N * K;
    }
    int n0 = blockIdx.x * 32, k0 = blockIdx.y * 32;
    int tx = threadIdx.x, ty = threadIdx.y;
#pragma unroll
    for (int j = 0; j < 4; j++)
        tf[ty + 8 * j][tx] = Wm[(size_t)(k0 + ty + 8 * j) * N + n0 + tx];
    __syncthreads();
    int pid = tx & 15, half = tx >> 4;
#pragma unroll
    for (int j = 0; j < 4; j++) {
        int nl = ty + 8 * j;
        float v0 = tf[2 * pid][nl], v1 = tf[2 * pid + 1][nl];
        if (half == 0) {
            uint32_t* dst = (uint32_t*)(Wh + (size_t)(n0 + nl) * K + k0);
            dst[pid] = packbf(v0, v1);
        } else {
            uint32_t* dst = (uint32_t*)(Wl + (size_t)(n0 + nl) * K + k0);
            dst[pid] = packbf(v0 - bf16r(v0), v1 - bf16r(v1));
        }
    }
}

// ---------------- HMMA grouped GEMM: 512 threads, 16 warps (4x4), 32x32/warp --
// smem: 3 stages x 4 planes (Ah,Al,Bh,Bl) x 128 rows x 80B = 122880 B
#define PLANE_B 10240
#define STAGE_B 40960
#define N_STAGE 3
#define SMEM_B  (N_STAGE * STAGE_B)

template <int G>   // 1 = gate/up + SiLU, 2 = down + weight scatter
__global__ void __launch_bounds__(512, 1) gemm_hmma_kernel() {
    int tile = blockIdx.y;
    if (tile >= d_num_tiles) return;
    const int e = d_tile_expert[tile];
    const int row0 = d_tile_row0[tile];
    const int rowend = d_tile_rowend[tile];
    const int nb = blockIdx.x;

    extern __shared__ char smem[];
    const uint32_t sb = smem_u32(smem);
    const int tid = threadIdx.x, wid = tid >> 5, lane = tid & 31;

    // ---- fill mapping: plane = tid>>7 (Ah,Al,Bh,Bl); one row per thread ----
    const int plane = tid >> 7, f = tid & 127;
    const __nv_bfloat16* p0 = d_x_h;
    int z0 = 16;
    if (plane < 2) {
        const __nv_bfloat16* bp = (G == 1) ? (plane ? d_x_l : d_x_h)
                                           : (plane ? d_hbuf_l : d_hbuf_h);
        int g0 = row0 + f;
        if (g0 < rowend) p0 = bp + (size_t)(G == 1 ? (d_perm[g0] >> 1) : g0) * 1024;
        else z0 = 0;
    } else {
        if (G == 1) {
            // interleaved gate/up: block col n -> unit nb*64+(n>>1); odd n = up
            const __nv_bfloat16* bp = ((plane == 3) ? d_upwT_l : d_upwT_h)
                                      + (size_t)e * 2 * I_DIM * H_DIM;
            int u = nb * 64 + (f >> 1);
            p0 = bp + (size_t)((f & 1) ? I_DIM + u : u) * 1024;
        } else {
            const __nv_bfloat16* bp = ((plane == 3) ? d_dnwT_l : d_dnwT_h)
                                      + (size_t)e * H_DIM * I_DIM;
            p0 = bp + (size_t)(nb * 128 + f) * 1024;
        }
    }
    const uint32_t dst0 = sb + plane * PLANE_B + f * 80;

    // ---- warp tiling: 4 m-warps x 4 n-warps; warp tile 32x32 ----
    const int warp_m = wid >> 2, warp_n = wid & 3;
    const uint32_t a_off = (uint32_t)((warp_m * 32 + (lane & 15)) * 80 + (lane >> 4) * 16);
    const uint32_t b_off = (uint32_t)((warp_n * 32 + ((lane >> 4) & 1) * 8 + (lane & 7)) * 80
                                      + ((lane >> 3) & 1) * 16);

    float acc[2][4][4];
#pragma unroll
    for (int mt = 0; mt < 2; mt++)
#pragma unroll
        for (int nt = 0; nt < 4; nt++)
#pragma unroll
            for (int q = 0; q < 4; q++) acc[mt][nt][q] = 0.f;

    auto fill = [&](int stage, int c) {
        uint32_t s0 = dst0 + stage * STAGE_B;
        const char* g0 = (const char*)(p0 + c * 64);   // 64 bf16 elems = 128B? no: ptr arith on bf16, chunk = 32 elems
        // NOTE: chunk covers 32 K-elements = 64 bytes; p0 + c*32 elems:
        g0 = (const char*)p0 + c * 64;                 // 64 bytes = 32 bf16 elems
#pragma unroll
        for (int s = 0; s < 4; s++) CP_ASYNC16(s0 + s * 16, g0 + s * 16, z0);
    };

    fill(0, 0); CP_COMMIT();
    fill(1, 1); CP_COMMIT();

    for (int c = 0; c < 32; c++) {
        if (c == 31) { CP_WAIT0(); } else { CP_WAIT1(); }
        __syncthreads();
        if (c + 2 < 32) { fill((c + 2) % N_STAGE, c + 2); CP_COMMIT(); }
        const uint32_t st = sb + (c % N_STAGE) * STAGE_B;
#pragma unroll
        for (int kb = 0; kb < 64; kb += 32) {
            uint32_t ah[2][4], al[2][4], bh[2][4], bl[2][4];
#pragma unroll
            for (int mt = 0; mt < 2; mt++) {
                uint32_t aa = st + a_off + mt * 1280 + kb;
                LDSM_X4(ah[mt][0], ah[mt][1], ah[mt][2], ah[mt][3], aa);
                LDSM_X4(al[mt][0], al[mt][1], al[mt][2], al[mt][3], aa + PLANE_B);
            }
#pragma unroll
            for (int bp2 = 0; bp2 < 2; bp2++) {
                uint32_t ba = st + 2 * PLANE_B + b_off + bp2 * 1280 + kb;
                LDSM_X4(bh[bp2][0], bh[bp2][1], bh[bp2][2], bh[bp2][3], ba);
                LDSM_X4(bl[bp2][0], bl[bp2][1], bl[bp2][2], bl[bp2][3], ba + PLANE_B);
            }
#pragma unroll
            for (int mt = 0; mt < 2; mt++)
#pragma unroll
                for (int nt = 0; nt < 4; nt++)
                    mma_bf16(acc[mt][nt], ah[mt],
                             bh[nt >> 1][(nt & 1) * 2], bh[nt >> 1][(nt & 1) * 2 + 1]);
#pragma unroll
            for (int mt = 0; mt < 2; mt++)
#pragma unroll
                for (int nt = 0; nt < 4; nt++)
                    mma_bf16(acc[mt][nt], al[mt],
                             bh[nt >> 1][(nt & 1) * 2], bh[nt >> 1][(nt & 1) * 2 + 1]);
#pragma unroll
            for (int mt = 0; mt < 2; mt++)
#pragma unroll
                for (int nt = 0; nt < 4; nt++)
                    mma_bf16(acc[mt][nt], ah[mt],
                             bl[nt >> 1][(nt & 1) * 2], bl[nt >> 1][(nt & 1) * 2 + 1]);
        }
        __syncthreads();
    }

    // ---- epilogue ----
    if (G == 1) {
#pragma unroll
        for (int mt = 0; mt < 2; mt++) {
            int rA = row0 + warp_m * 32 + mt * 16 + (lane >> 2);
            int rB = rA + 8;
#pragma unroll
            for (int nt = 0; nt < 4; nt++) {
                // block col pair (even,odd) = (gate,up) of unit:
                int col = nb * 64 + warp_n * 16 + nt * 4 + (lane & 3);
                float* d = acc[mt][nt];
                if (rA < rowend) {
                    float g = d[0], u = d[1];
                    float h = g / (1.f + expf(-g)) * u;
                    d_hbuf_h[(size_t)rA * 1024 + col] = __float2bfloat16(h);
                    d_hbuf_l[(size_t)rA * 1024 + col] = __float2bfloat16(h - bf16r(h));
                }
                if (rB < rowend) {
                    float g = d[2], u = d[3];
                    float h = g / (1.f + expf(-g)) * u;
                    d_hbuf_h[(size_t)rB * 1024 + col] = __float2bfloat16(h);
                    d_hbuf_l[(size_t)rB * 1024 + col] = __float2bfloat16(h - bf16r(h));
                }
            }
        }
    } else {
#pragma unroll
        for (int mt = 0; mt < 2; mt++) {
            int rA = row0 + warp_m * 32 + mt * 16 + (lane >> 2);
            int rB = rA + 8;
            if (rA < rowend) {
                int slot = d_perm[rA];
                float w = d_w_of_slot[slot];
                float* po = &d_acc[(size_t)slot * 1024 + nb * 128 + warp_n * 32 + 2 * (lane & 3)];
#pragma unroll
                for (int nt = 0; nt < 4; nt++) {
                    float* d = acc[mt][nt];
                    *(float2*)(po + nt * 8) = make_float2(w * d[0], w * d[1]);
                }
            }
            if (rB < rowend) {
                int slot = d_perm[rB];
                float w = d_w_of_slot[slot];
                float* po = &d_acc[(size_t)slot * 1024 + nb * 128 + warp_n * 32 + 2 * (lane & 3)];
#pragma unroll
                for (int nt = 0; nt < 4; nt++) {
                    float* d = acc[mt][nt];
                    *(float2*)(po + nt * 8) = make_float2(w * d[2], w * d[3]);
                }
            }
        }
    }
}

// ---------------- combine: out[t] = acc[2t] + acc[2t+1] ----------------
__global__ void combine_kernel(float* __restrict__ out) {
    int i = blockIdx.x * blockDim.x + threadIdx.x;
    int t = i / (H_DIM / 4);
    int c = i % (H_DIM / 4);
    const float4* a0 = (const float4*)&d_acc[(size_t)(2 * t) * H_DIM];
    const float4* a1 = (const float4*)&d_acc[(size_t)(2 * t + 1) * H_DIM];
    float4 x0 = a0[c], x1 = a1[c];
    ((float4*)out)[i] = make_float4(x0.x + x1.x, x0.y + x1.y, x0.z + x1.z, x0.w + x1.w);
}

// ---------------- launch ----------------
extern "C" void kernel_launch(void* const* d_in, const int* in_sizes, int n_in,
                              void* d_out, int out_size) {
    (void)in_sizes; (void)n_in; (void)out_size;
    const float* x      = (const float*)d_in[0];
    const float* logits = (const float*)d_in[1];
    const float* up_w   = (const float*)d_in[2];
    const float* down_w = (const float*)d_in[3];
    float* out = (float*)d_out;

    cudaFuncSetAttribute(gemm_hmma_kernel<1>, cudaFuncAttributeMaxDynamicSharedMemorySize, SMEM_B);
    cudaFuncSetAttribute(gemm_hmma_kernel<2>, cudaFuncAttributeMaxDynamicSharedMemorySize, SMEM_B);

    conv_x_kernel<<<T_TOK * H_DIM / 4 / 256, 256>>>(x);            // launch 0 (zeroes counts too)
    router_kernel<<<T_TOK / 256, 256>>>(logits);                   // 1
    setup_kernel<<<1, 256>>>();                                    // 2
    conv_w_kernel<<<dim3(64, 32, 2 * E_NUM), dim3(32, 8)>>>(up_w, down_w);  // 3
    gemm_hmma_kernel<1><<<dim3(16, MAX_TILES), 512, SMEM_B>>>();   // 4
    gemm_hmma_kernel<2><<<dim3(8, MAX_TILES), 512, SMEM_B>>>();    // 5
    combine_kernel<<<T_TOK * H_DIM / 4 / 256, 256>>>(out);         // 6
}

// round 6
// speedup vs baseline: 1.6317x; 1.6246x over previous
#include <cuda_runtime.h>
#include <cuda_bf16.h>
#include <cstdint>

#define T_TOK 4096
#define H_DIM 1024
#define I_DIM 1024
#define E_NUM 8
#define S_SLOTS (T_TOK * 2)
#define BM 128
#define MAX_TILES (S_SLOTS / BM + E_NUM)   // 72
#define NCHUNK 32                          // K chunks of 32 elems (64B/row)
#define BLK_B 8192                         // one operand block: 128 rows x 64B

// ---------------- device scratch ----------------
__device__ int   d_counts[E_NUM];
__device__ int   d_expert_of_slot[S_SLOTS];
__device__ float d_w_of_slot[S_SLOTS];
__device__ int   d_perm[S_SLOTS];
__device__ int   d_tile_expert[MAX_TILES];
__device__ int   d_tile_row0[MAX_TILES];
__device__ int   d_tile_rowend[MAX_TILES];
__device__ int   d_num_tiles;

// block-chunked operands: [blockIdx][chunk] -> 8KB (128 rows x 64B, swizzled)
__device__ __align__(16) __nv_bfloat16 d_ag_h[(size_t)MAX_TILES * NCHUNK * 4096];
__device__ __align__(16) __nv_bfloat16 d_ag_l[(size_t)MAX_TILES * NCHUNK * 4096];
__device__ __align__(16) __nv_bfloat16 d_upwB_h[(size_t)E_NUM * 16 * NCHUNK * 4096];
__device__ __align__(16) __nv_bfloat16 d_upwB_l[(size_t)E_NUM * 16 * NCHUNK * 4096];
__device__ __align__(16) __nv_bfloat16 d_dnwB_h[(size_t)E_NUM * 8 * NCHUNK * 4096];
__device__ __align__(16) __nv_bfloat16 d_dnwB_l[(size_t)E_NUM * 8 * NCHUNK * 4096];
__device__ __align__(16) __nv_bfloat16 d_hbuf_h[(size_t)MAX_TILES * NCHUNK * 4096];
__device__ __align__(16) __nv_bfloat16 d_hbuf_l[(size_t)MAX_TILES * NCHUNK * 4096];
__device__ __align__(16) float d_acc[(size_t)S_SLOTS * H_DIM];

// ---------------- PTX helpers ----------------
__device__ __forceinline__ uint32_t smem_u32(const void* p) {
    uint32_t a;
    asm("{ .reg .u64 t; cvta.to.shared.u64 t, %1; cvt.u32.u64 %0, t; }" : "=r"(a) : "l"(p));
    return a;
}
#define MBAR_INIT(a, c) asm volatile("mbarrier.init.shared.b64 [%0], %1;" :: "r"(a), "r"(c) : "memory")
#define MBAR_EXPECT_TX(a, b) \
    asm volatile("mbarrier.arrive.expect_tx.shared.b64 _, [%0], %1;" :: "r"(a), "r"(b) : "memory")
#define MBAR_WAIT(a, ph) do {                                                            \
    uint32_t _m = (a), _p = (ph), _d;                                                    \
    asm volatile("{ .reg .pred p; mbarrier.try_wait.parity.acquire.cta.shared::cta.b64 " \
                 "p, [%1], %2; selp.b32 %0, 1, 0, p; }"                                  \
                 : "=r"(_d) : "r"(_m), "r"(_p) : "memory");                              \
    if (!_d) {                                                                           \
        asm volatile("{ .reg .pred P1; WL_%=: mbarrier.try_wait.parity.acquire.cta."     \
                     "shared::cta.b64 P1, [%0], %1, 0x989680; @P1 bra.uni WD_%=; "       \
                     "bra.uni WL_%=; WD_%=: }" :: "r"(_m), "r"(_p) : "memory");          \
    }                                                                                    \
} while (0)
#define BULK_G2S(dst, src, sz, mbar) \
    asm volatile("cp.async.bulk.shared::cluster.global.mbarrier::complete_tx::bytes " \
                 "[%0], [%1], %2, [%3];" :: "r"(dst), "l"(src), "r"(sz), "r"(mbar) : "memory")
#define LDSM_X4(r0, r1, r2, r3, addr) \
    asm volatile("ldmatrix.sync.aligned.m8n8.x4.shared.b16 {%0,%1,%2,%3}, [%4];" \
        : "=r"(r0), "=r"(r1), "=r"(r2), "=r"(r3) : "r"(addr))

__device__ __forceinline__ void mma_bf16(float* d, const uint32_t* a, uint32_t b0, uint32_t b1) {
    asm volatile("mma.sync.aligned.m16n8k16.row.col.f32.bf16.bf16.f32 "
        "{%0,%1,%2,%3}, {%4,%5,%6,%7}, {%8,%9}, {%0,%1,%2,%3};"
        : "+f"(d[0]), "+f"(d[1]), "+f"(d[2]), "+f"(d[3])
        : "r"(a[0]), "r"(a[1]), "r"(a[2]), "r"(a[3]), "r"(b0), "r"(b1));
}
__device__ __forceinline__ uint32_t packbf(float a, float b) {  // a->lo, b->hi
    uint32_t r;
    asm("cvt.rn.bf16x2.f32 %0, %1, %2;" : "=r"(r) : "f"(b), "f"(a));
    return r;
}
__device__ __forceinline__ float bf16r(float v) {
    return __bfloat162float(__float2bfloat16(v));
}

// split 32 fp32 -> hi/lo bf16 rows (64B each), store swizzled
__device__ __forceinline__ void store_split64(char* bh, char* bl, uint32_t off0,
                                              uint32_t swm, const float* v) {
    uint32_t hi[16], lo[16];
#pragma unroll
    for (int j = 0; j < 16; j++) {
        float a = v[2 * j], b = v[2 * j + 1];
        hi[j] = packbf(a, b);
        lo[j] = packbf(a - bf16r(a), b - bf16r(b));
    }
#pragma unroll
    for (int g = 0; g < 4; g++) {
        uint32_t o = (off0 + g * 16) ^ swm;
        *(uint4*)(bh + o) = make_uint4(hi[4 * g], hi[4 * g + 1], hi[4 * g + 2], hi[4 * g + 3]);
        *(uint4*)(bl + o) = make_uint4(lo[4 * g], lo[4 * g + 1], lo[4 * g + 2], lo[4 * g + 3]);
    }
}

// ---------------- router + sort ----------------
__global__ void zero_counts_kernel() {
    if (threadIdx.x < E_NUM) d_counts[threadIdx.x] = 0;
}
__global__ void router_kernel(const float* __restrict__ logits) {
    int t = blockIdx.x * blockDim.x + threadIdx.x;
    if (t >= T_TOK) return;
    float l[E_NUM];
#pragma unroll
    for (int e = 0; e < E_NUM; e++) l[e] = logits[t * E_NUM + e];
    int i0 = 0;
#pragma unroll
    for (int e = 1; e < E_NUM; e++) if (l[e] > l[i0]) i0 = e;
    int i1 = (i0 == 0) ? 1 : 0;
#pragma unroll
    for (int e = 0; e < E_NUM; e++) {
        if (e == i0 || e == i1) continue;
        if (l[e] > l[i1]) i1 = e;
    }
    float w0 = 1.f / (1.f + expf(l[i1] - l[i0]));
    d_expert_of_slot[2 * t] = i0; d_expert_of_slot[2 * t + 1] = i1;
    d_w_of_slot[2 * t] = w0;      d_w_of_slot[2 * t + 1] = 1.f - w0;
    atomicAdd(&d_counts[i0], 1);
    atomicAdd(&d_counts[i1], 1);
}
__global__ void setup_kernel() {
    __shared__ int s_off[E_NUM];
    __shared__ int s_cur[E_NUM];
    if (threadIdx.x == 0) {
        int acc = 0, nt = 0;
        for (int e = 0; e < E_NUM; e++) {
            int c = d_counts[e];
            s_off[e] = acc;
            for (int r = 0; r < c; r += BM) {
                d_tile_expert[nt] = e;
                d_tile_row0[nt] = acc + r;
                d_tile_rowend[nt] = acc + c;
                nt++;
            }
            acc += c;
        }
        d_num_tiles = nt;
    }
    if (threadIdx.x < E_NUM) s_cur[threadIdx.x] = 0;
    __syncthreads();
    for (int s = threadIdx.x; s < S_SLOTS; s += blockDim.x) {
        int e = d_expert_of_slot[s];
        int pos = s_off[e] + atomicAdd(&s_cur[e], 1);
        d_perm[pos] = s;
    }
}

// ---------------- prepass: gathered A blocks for GEMM1 ----------------
// grid (NCHUNK, MAX_TILES), 128 threads; OOB rows -> zeros
__global__ void gather_a_kernel(const float* __restrict__ x) {
    int tile = blockIdx.y;
    if (tile >= d_num_tiles) return;
    int c = blockIdx.x, r = threadIdx.x;
    int row0 = d_tile_row0[tile], rowend = d_tile_rowend[tile];
    size_t blk = ((size_t)tile * NCHUNK + c) * BLK_B;
    char* bh = (char*)d_ag_h + blk;
    char* bl = (char*)d_ag_l + blk;
    uint32_t off0 = r * 64, swm = ((r >> 1) & 7) << 4;
    if (row0 + r < rowend) {
        int token = d_perm[row0 + r] >> 1;
        const float4* src = (const float4*)(x + (size_t)token * H_DIM + c * 32);
        float v[32];
#pragma unroll
        for (int j = 0; j < 8; j++) {
            float4 q = src[j];
            v[4 * j] = q.x; v[4 * j + 1] = q.y; v[4 * j + 2] = q.z; v[4 * j + 3] = q.w;
        }
        store_split64(bh, bl, off0, swm, v);
    } else {
        uint4 z = make_uint4(0, 0, 0, 0);
#pragma unroll
        for (int g = 0; g < 4; g++) {
            uint32_t o = (off0 + g * 16) ^ swm;
            *(uint4*)(bh + o) = z;
            *(uint4*)(bl + o) = z;
        }
    }
}

// ---------------- prepass: weights -> block layout ----------------
// grid (24, NCHUNK, E_NUM): x<16 -> up (interleaved gate/up rows), else down
__global__ void conv_w_kernel(const float* __restrict__ up_w,
                              const float* __restrict__ dn_w) {
    int e = blockIdx.z, c = blockIdx.y, bx = blockIdx.x, r = threadIdx.x;
    const float* src;
    char *bh, *bl;
    int N, ncol;
    if (bx < 16) {
        N = 2 * I_DIM;
        src = up_w + (size_t)e * H_DIM * N;
        int u = bx * 64 + (r >> 1);
        ncol = (r & 1) ? I_DIM + u : u;
        size_t blk = (((size_t)e * 16 + bx) * NCHUNK + c) * BLK_B;
        bh = (char*)d_upwB_h + blk; bl = (char*)d_upwB_l + blk;
    } else {
        N = H_DIM;
        src = dn_w + (size_t)e * I_DIM * N;
        ncol = (bx - 16) * 128 + r;
        size_t blk = (((size_t)e * 8 + (bx - 16)) * NCHUNK + c) * BLK_B;
        bh = (char*)d_dnwB_h + blk; bl = (char*)d_dnwB_l + blk;
    }
    float v[32];
#pragma unroll
    for (int j = 0; j < 32; j++) v[j] = src[(size_t)(c * 32 + j) * N + ncol];
    store_split64(bh, bl, r * 64, ((r >> 1) & 7) << 4, v);
}

// ---------------- bulk-copy HMMA grouped GEMM ----------------
// smem: 3 stages x 32KB (Ah|Al|Bh|Bl, 8KB each) + 3 mbarriers
#define STAGE_B 32768
#define MB_OFF  (3 * STAGE_B)
#define SMEM_B  (MB_OFF + 64)

template <int G>   // 1 = gate/up + SiLU -> hbuf blocks; 2 = down -> d_acc
__global__ void __launch_bounds__(512, 1) gemm_bulk_kernel() {
    int tile = blockIdx.y;
    if (tile >= d_num_tiles) return;
    const int e = d_tile_expert[tile];
    const int row0 = d_tile_row0[tile];
    const int rowend = d_tile_rowend[tile];
    const int nb = blockIdx.x;

    extern __shared__ char smem[];
    const uint32_t sb = smem_u32(smem);
    const int tid = threadIdx.x, wid = tid >> 5, lane = tid & 31;

    // global block bases
    const char* Ah = (const char*)((G == 1) ? d_ag_h : d_hbuf_h) + (size_t)tile * NCHUNK * BLK_B;
    const char* Al = (const char*)((G == 1) ? d_ag_l : d_hbuf_l) + (size_t)tile * NCHUNK * BLK_B;
    const char* Bh;
    const char* Bl;
    if (G == 1) {
        size_t wb = ((size_t)e * 16 + nb) * NCHUNK * BLK_B;
        Bh = (const char*)d_upwB_h + wb; Bl = (const char*)d_upwB_l + wb;
    } else {
        size_t wb = ((size_t)e * 8 + nb) * NCHUNK * BLK_B;
        Bh = (const char*)d_dnwB_h + wb; Bl = (const char*)d_dnwB_l + wb;
    }

    if (tid == 0) {
#pragma unroll
        for (int s = 0; s < 3; s++) MBAR_INIT(sb + MB_OFF + s * 8, 1);
    }
    __syncthreads();

    auto fill = [&](int s, int c) {
        uint32_t mb = sb + MB_OFF + s * 8;
        uint32_t st = sb + s * STAGE_B;
        MBAR_EXPECT_TX(mb, (uint32_t)STAGE_B);
        BULK_G2S(st,          Ah + (size_t)c * BLK_B, (uint32_t)BLK_B, mb);
        BULK_G2S(st + 8192,   Al + (size_t)c * BLK_B, (uint32_t)BLK_B, mb);
        BULK_G2S(st + 16384,  Bh + (size_t)c * BLK_B, (uint32_t)BLK_B, mb);
        BULK_G2S(st + 24576,  Bl + (size_t)c * BLK_B, (uint32_t)BLK_B, mb);
    };
    if (tid == 0) { fill(0, 0); fill(1, 1); fill(2, 2); }

    // ---- warp tiling: 4 m-warps x 4 n-warps; warp tile 32x32 ----
    const int warp_m = wid >> 2, warp_n = wid & 3;
    const int a_row = warp_m * 32 + (lane & 15);
    const uint32_t a_o0 = (uint32_t)(a_row * 64 + (lane >> 4) * 16);
    const uint32_t swm_a = (uint32_t)(((a_row >> 1) & 7) << 4);
    const int b_row = warp_n * 32 + ((lane >> 4) & 1) * 8 + (lane & 7);
    const uint32_t b_o0 = (uint32_t)(b_row * 64 + ((lane >> 3) & 1) * 16);
    const uint32_t swm_b = (uint32_t)(((b_row >> 1) & 7) << 4);

    float acc[2][4][4];
#pragma unroll
    for (int mt = 0; mt < 2; mt++)
#pragma unroll
        for (int nt = 0; nt < 4; nt++)
#pragma unroll
            for (int q = 0; q < 4; q++) acc[mt][nt][q] = 0.f;

    for (int c = 0; c < NCHUNK; c++) {
        const int s = c % 3;
        MBAR_WAIT(sb + MB_OFF + s * 8, (c / 3) & 1);
        const uint32_t st = sb + s * STAGE_B;
#pragma unroll
        for (int kb = 0; kb < 64; kb += 32) {
            uint32_t ah[2][4], al[2][4], bh[2][4], bl[2][4];
#pragma unroll
            for (int mt = 0; mt < 2; mt++) {
                uint32_t ao = (a_o0 + mt * 1024 + kb) ^ swm_a;
                LDSM_X4(ah[mt][0], ah[mt][1], ah[mt][2], ah[mt][3], st + ao);
                LDSM_X4(al[mt][0], al[mt][1], al[mt][2], al[mt][3], st + 8192 + ao);
            }
#pragma unroll
            for (int bp = 0; bp < 2; bp++) {
                uint32_t bo = (b_o0 + bp * 1024 + kb) ^ swm_b;
                LDSM_X4(bh[bp][0], bh[bp][1], bh[bp][2], bh[bp][3], st + 16384 + bo);
                LDSM_X4(bl[bp][0], bl[bp][1], bl[bp][2], bl[bp][3], st + 24576 + bo);
            }
#pragma unroll
            for (int mt = 0; mt < 2; mt++)
#pragma unroll
                for (int nt = 0; nt < 4; nt++)
                    mma_bf16(acc[mt][nt], ah[mt],
                             bh[nt >> 1][(nt & 1) * 2], bh[nt >> 1][(nt & 1) * 2 + 1]);
#pragma unroll
            for (int mt = 0; mt < 2; mt++)
#pragma unroll
                for (int nt = 0; nt < 4; nt++)
                    mma_bf16(acc[mt][nt], al[mt],
                             bh[nt >> 1][(nt & 1) * 2], bh[nt >> 1][(nt & 1) * 2 + 1]);
#pragma unroll
            for (int mt = 0; mt < 2; mt++)
#pragma unroll
                for (int nt = 0; nt < 4; nt++)
                    mma_bf16(acc[mt][nt], ah[mt],
                             bl[nt >> 1][(nt & 1) * 2], bl[nt >> 1][(nt & 1) * 2 + 1]);
        }
        __syncthreads();
        if (c + 3 < NCHUNK && tid == 0) fill(s, c + 3);
    }

    // ---- epilogue ----
    if (G == 1) {
        // write h into hbuf blocks (block layout, swizzled); OOB rows are 0 already
        char* hb = (char*)d_hbuf_h + (size_t)tile * NCHUNK * BLK_B;
        char* lb = (char*)d_hbuf_l + (size_t)tile * NCHUNK * BLK_B;
#pragma unroll
        for (int mt = 0; mt < 2; mt++) {
            int rA = warp_m * 32 + mt * 16 + (lane >> 2);   // local row
            int rB = rA + 8;
#pragma unroll
            for (int nt = 0; nt < 4; nt++) {
                int hc = nb * 64 + warp_n * 16 + nt * 4 + (lane & 3);
                size_t blk = (size_t)(hc >> 5) * BLK_B;
                int coff = (hc & 31) * 2;
                float* d = acc[mt][nt];
                {
                    float g = d[0], u = d[1];
                    float h = g / (1.f + expf(-g)) * u;
                    uint32_t o = (uint32_t)(rA * 64 + coff) ^ (uint32_t)(((rA >> 1) & 7) << 4);
                    *(__nv_bfloat16*)(hb + blk + o) = __float2bfloat16(h);
                    *(__nv_bfloat16*)(lb + blk + o) = __float2bfloat16(h - bf16r(h));
                }
                {
                    float g = d[2], u = d[3];
                    float h = g / (1.f + expf(-g)) * u;
                    uint32_t o = (uint32_t)(rB * 64 + coff) ^ (uint32_t)(((rB >> 1) & 7) << 4);
                    *(__nv_bfloat16*)(hb + blk + o) = __float2bfloat16(h);
                    *(__nv_bfloat16*)(lb + blk + o) = __float2bfloat16(h - bf16r(h));
                }
            }
        }
    } else {
#pragma unroll
        for (int mt = 0; mt < 2; mt++) {
            int rA = row0 + warp_m * 32 + mt * 16 + (lane >> 2);
            int rB = rA + 8;
            if (rA < rowend) {
                int slot = d_perm[rA];
                float w = d_w_of_slot[slot];
                float* po = &d_acc[(size_t)slot * H_DIM + nb * 128 + warp_n * 32 + 2 * (lane & 3)];
#pragma unroll
                for (int nt = 0; nt < 4; nt++) {
                    float* d = acc[mt][nt];
                    *(float2*)(po + nt * 8) = make_float2(w * d[0], w * d[1]);
                }
            }
            if (rB < rowend) {
                int slot = d_perm[rB];
                float w = d_w_of_slot[slot];
                float* po = &d_acc[(size_t)slot * H_DIM + nb * 128 + warp_n * 32 + 2 * (lane & 3)];
#pragma unroll
                for (int nt = 0; nt < 4; nt++) {
                    float* d = acc[mt][nt];
                    *(float2*)(po + nt * 8) = make_float2(w * d[2], w * d[3]);
                }
            }
        }
    }
}

// ---------------- combine: out[t] = acc[2t] + acc[2t+1] ----------------
__global__ void combine_kernel(float* __restrict__ out) {
    int i = blockIdx.x * blockDim.x + threadIdx.x;
    int t = i / (H_DIM / 4);
    int c = i % (H_DIM / 4);
    const float4* a0 = (const float4*)&d_acc[(size_t)(2 * t) * H_DIM];
    const float4* a1 = (const float4*)&d_acc[(size_t)(2 * t + 1) * H_DIM];
    float4 x0 = a0[c], x1 = a1[c];
    ((float4*)out)[i] = make_float4(x0.x + x1.x, x0.y + x1.y, x0.z + x1.z, x0.w + x1.w);
}

// ---------------- launch ----------------
extern "C" void kernel_launch(void* const* d_in, const int* in_sizes, int n_in,
                              void* d_out, int out_size) {
    (void)in_sizes; (void)n_in; (void)out_size;
    const float* x      = (const float*)d_in[0];
    const float* logits = (const float*)d_in[1];
    const float* up_w   = (const float*)d_in[2];
    const float* down_w = (const float*)d_in[3];
    float* out = (float*)d_out;

    cudaFuncSetAttribute(gemm_bulk_kernel<1>, cudaFuncAttributeMaxDynamicSharedMemorySize, SMEM_B);
    cudaFuncSetAttribute(gemm_bulk_kernel<2>, cudaFuncAttributeMaxDynamicSharedMemorySize, SMEM_B);

    zero_counts_kernel<<<1, 32>>>();                                         // 0
    router_kernel<<<T_TOK / 256, 256>>>(logits);                             // 1
    setup_kernel<<<1, 256>>>();                                              // 2
    gather_a_kernel<<<dim3(NCHUNK, MAX_TILES), 128>>>(x);                    // 3
    conv_w_kernel<<<dim3(24, NCHUNK, E_NUM), 128>>>(up_w, down_w);           // 4
    gemm_bulk_kernel<1><<<dim3(16, MAX_TILES), 512, SMEM_B>>>();             // 5
    gemm_bulk_kernel<2><<<dim3(8, MAX_TILES), 512, SMEM_B>>>();              // 6
    combine_kernel<<<T_TOK * H_DIM / 4 / 256, 256>>>(out);                   // 7
}

// round 7
// speedup vs baseline: 1.8866x; 1.1562x over previous
#include <cuda_runtime.h>
#include <cuda_bf16.h>
#include <cstdint>

#define T_TOK 4096
#define H_DIM 1024
#define I_DIM 1024
#define E_NUM 8
#define S_SLOTS (T_TOK * 2)
#define BM 128
#define MAX_TILES (S_SLOTS / BM + E_NUM)   // 72
#define NCHUNK 32                          // K chunks of 32 elems (64B/row)
#define BLK_B 8192                         // one operand block: 128 rows x 64B

// ---------------- device scratch ----------------
__device__ int   d_counts[E_NUM];
__device__ int   d_expert_of_slot[S_SLOTS];
__device__ float d_w_of_slot[S_SLOTS];
__device__ int   d_perm[S_SLOTS];
__device__ int   d_tile_expert[MAX_TILES];
__device__ int   d_tile_row0[MAX_TILES];
__device__ int   d_tile_rowend[MAX_TILES];
__device__ int   d_num_tiles;

// block-chunked operands: [blockIdx][chunk] -> 8KB (128 rows x 64B, swizzled)
__device__ __align__(16) __nv_bfloat16 d_ag_h[(size_t)MAX_TILES * NCHUNK * 4096];
__device__ __align__(16) __nv_bfloat16 d_ag_l[(size_t)MAX_TILES * NCHUNK * 4096];
__device__ __align__(16) __nv_bfloat16 d_upwB_h[(size_t)E_NUM * 16 * NCHUNK * 4096];
__device__ __align__(16) __nv_bfloat16 d_upwB_l[(size_t)E_NUM * 16 * NCHUNK * 4096];
__device__ __align__(16) __nv_bfloat16 d_dnwB_h[(size_t)E_NUM * 8 * NCHUNK * 4096];
__device__ __align__(16) __nv_bfloat16 d_dnwB_l[(size_t)E_NUM * 8 * NCHUNK * 4096];
__device__ __align__(16) __nv_bfloat16 d_hbuf_h[(size_t)MAX_TILES * NCHUNK * 4096];
__device__ __align__(16) __nv_bfloat16 d_hbuf_l[(size_t)MAX_TILES * NCHUNK * 4096];
__device__ __align__(16) float d_acc[(size_t)S_SLOTS * H_DIM];

// ---------------- PTX helpers ----------------
__device__ __forceinline__ uint32_t smem_u32(const void* p) {
    uint32_t a;
    asm("{ .reg .u64 t; cvta.to.shared.u64 t, %1; cvt.u32.u64 %0, t; }" : "=r"(a) : "l"(p));
    return a;
}
#define MBAR_INIT(a, c) asm volatile("mbarrier.init.shared.b64 [%0], %1;" :: "r"(a), "r"(c) : "memory")
#define MBAR_EXPECT_TX(a, b) \
    asm volatile("mbarrier.arrive.expect_tx.shared.b64 _, [%0], %1;" :: "r"(a), "r"(b) : "memory")
#define MBAR_WAIT(a, ph) do {                                                            \
    uint32_t _m = (a), _p = (ph), _d;                                                    \
    asm volatile("{ .reg .pred p; mbarrier.try_wait.parity.acquire.cta.shared::cta.b64 " \
                 "p, [%1], %2; selp.b32 %0, 1, 0, p; }"                                  \
                 : "=r"(_d) : "r"(_m), "r"(_p) : "memory");                              \
    if (!_d) {                                                                           \
        asm volatile("{ .reg .pred P1; WL_%=: mbarrier.try_wait.parity.acquire.cta."     \
                     "shared::cta.b64 P1, [%0], %1, 0x989680; @P1 bra.uni WD_%=; "       \
                     "bra.uni WL_%=; WD_%=: }" :: "r"(_m), "r"(_p) : "memory");          \
    }                                                                                    \
} while (0)
#define BULK_G2S(dst, src, sz, mbar) \
    asm volatile("cp.async.bulk.shared::cluster.global.mbarrier::complete_tx::bytes " \
                 "[%0], [%1], %2, [%3];" :: "r"(dst), "l"(src), "r"(sz), "r"(mbar) : "memory")
#define LDSM_X4(r0, r1, r2, r3, addr) \
    asm volatile("ldmatrix.sync.aligned.m8n8.x4.shared.b16 {%0,%1,%2,%3}, [%4];" \
        : "=r"(r0), "=r"(r1), "=r"(r2), "=r"(r3) : "r"(addr))

__device__ __forceinline__ void mma_bf16(float* d, const uint32_t* a, uint32_t b0, uint32_t b1) {
    asm volatile("mma.sync.aligned.m16n8k16.row.col.f32.bf16.bf16.f32 "
        "{%0,%1,%2,%3}, {%4,%5,%6,%7}, {%8,%9}, {%0,%1,%2,%3};"
        : "+f"(d[0]), "+f"(d[1]), "+f"(d[2]), "+f"(d[3])
        : "r"(a[0]), "r"(a[1]), "r"(a[2]), "r"(a[3]), "r"(b0), "r"(b1));
}
__device__ __forceinline__ uint32_t packbf(float a, float b) {  // a->lo, b->hi
    uint32_t r;
    asm("cvt.rn.bf16x2.f32 %0, %1, %2;" : "=r"(r) : "f"(b), "f"(a));
    return r;
}
__device__ __forceinline__ float bf16r(float v) {
    return __bfloat162float(__float2bfloat16(v));
}

// split 32 fp32 -> hi/lo bf16 rows (64B each), store swizzled
__device__ __forceinline__ void store_split64(char* bh, char* bl, uint32_t off0,
                                              uint32_t swm, const float* v) {
    uint32_t hi[16], lo[16];
#pragma unroll
    for (int j = 0; j < 16; j++) {
        float a = v[2 * j], b = v[2 * j + 1];
        hi[j] = packbf(a, b);
        lo[j] = packbf(a - bf16r(a), b - bf16r(b));
    }
#pragma unroll
    for (int g = 0; g < 4; g++) {
        uint32_t o = (off0 + g * 16) ^ swm;
        *(uint4*)(bh + o) = make_uint4(hi[4 * g], hi[4 * g + 1], hi[4 * g + 2], hi[4 * g + 3]);
        *(uint4*)(bl + o) = make_uint4(lo[4 * g], lo[4 * g + 1], lo[4 * g + 2], lo[4 * g + 3]);
    }
}

// ---------------- router + sort ----------------
__global__ void zero_counts_kernel() {
    if (threadIdx.x < E_NUM) d_counts[threadIdx.x] = 0;
}
__global__ void router_kernel(const float* __restrict__ logits) {
    int t = blockIdx.x * blockDim.x + threadIdx.x;
    if (t >= T_TOK) return;
    float l[E_NUM];
#pragma unroll
    for (int e = 0; e < E_NUM; e++) l[e] = logits[t * E_NUM + e];
    int i0 = 0;
#pragma unroll
    for (int e = 1; e < E_NUM; e++) if (l[e] > l[i0]) i0 = e;
    int i1 = (i0 == 0) ? 1 : 0;
#pragma unroll
    for (int e = 0; e < E_NUM; e++) {
        if (e == i0 || e == i1) continue;
        if (l[e] > l[i1]) i1 = e;
    }
    float w0 = 1.f / (1.f + expf(l[i1] - l[i0]));
    d_expert_of_slot[2 * t] = i0; d_expert_of_slot[2 * t + 1] = i1;
    d_w_of_slot[2 * t] = w0;      d_w_of_slot[2 * t + 1] = 1.f - w0;
    atomicAdd(&d_counts[i0], 1);
    atomicAdd(&d_counts[i1], 1);
}
__global__ void setup_kernel() {
    __shared__ int s_off[E_NUM];
    __shared__ int s_cur[E_NUM];
    if (threadIdx.x == 0) {
        int acc = 0, nt = 0;
        for (int e = 0; e < E_NUM; e++) {
            int c = d_counts[e];
            s_off[e] = acc;
            for (int r = 0; r < c; r += BM) {
                d_tile_expert[nt] = e;
                d_tile_row0[nt] = acc + r;
                d_tile_rowend[nt] = acc + c;
                nt++;
            }
            acc += c;
        }
        d_num_tiles = nt;
    }
    if (threadIdx.x < E_NUM) s_cur[threadIdx.x] = 0;
    __syncthreads();
    for (int s = threadIdx.x; s < S_SLOTS; s += blockDim.x) {
        int e = d_expert_of_slot[s];
        int pos = s_off[e] + atomicAdd(&s_cur[e], 1);
        d_perm[pos] = s;
    }
}

// ---------------- prepass: gathered A blocks for GEMM1 ----------------
__global__ void gather_a_kernel(const float* __restrict__ x) {
    int tile = blockIdx.y;
    if (tile >= d_num_tiles) return;
    int c = blockIdx.x, r = threadIdx.x;
    int row0 = d_tile_row0[tile], rowend = d_tile_rowend[tile];
    size_t blk = ((size_t)tile * NCHUNK + c) * BLK_B;
    char* bh = (char*)d_ag_h + blk;
    char* bl = (char*)d_ag_l + blk;
    uint32_t off0 = r * 64, swm = ((r >> 1) & 7) << 4;
    if (row0 + r < rowend) {
        int token = d_perm[row0 + r] >> 1;
        const float4* src = (const float4*)(x + (size_t)token * H_DIM + c * 32);
        float v[32];
#pragma unroll
        for (int j = 0; j < 8; j++) {
            float4 q = src[j];
            v[4 * j] = q.x; v[4 * j + 1] = q.y; v[4 * j + 2] = q.z; v[4 * j + 3] = q.w;
        }
        store_split64(bh, bl, off0, swm, v);
    } else {
        uint4 z = make_uint4(0, 0, 0, 0);
#pragma unroll
        for (int g = 0; g < 4; g++) {
            uint32_t o = (off0 + g * 16) ^ swm;
            *(uint4*)(bh + o) = z;
            *(uint4*)(bl + o) = z;
        }
    }
}

// ---------------- prepass: weights -> block layout ----------------
__global__ void conv_w_kernel(const float* __restrict__ up_w,
                              const float* __restrict__ dn_w) {
    int e = blockIdx.z, c = blockIdx.y, bx = blockIdx.x, r = threadIdx.x;
    const float* src;
    char *bh, *bl;
    int N, ncol;
    if (bx < 16) {
        N = 2 * I_DIM;
        src = up_w + (size_t)e * H_DIM * N;
        int u = bx * 64 + (r >> 1);
        ncol = (r & 1) ? I_DIM + u : u;
        size_t blk = (((size_t)e * 16 + bx) * NCHUNK + c) * BLK_B;
        bh = (char*)d_upwB_h + blk; bl = (char*)d_upwB_l + blk;
    } else {
        N = H_DIM;
        src = dn_w + (size_t)e * I_DIM * N;
        ncol = (bx - 16) * 128 + r;
        size_t blk = (((size_t)e * 8 + (bx - 16)) * NCHUNK + c) * BLK_B;
        bh = (char*)d_dnwB_h + blk; bl = (char*)d_dnwB_l + blk;
    }
    float v[32];
#pragma unroll
    for (int j = 0; j < 32; j++) v[j] = src[(size_t)(c * 32 + j) * N + ncol];
    store_split64(bh, bl, r * 64, ((r >> 1) & 7) << 4, v);
}

// ---------------- bulk-copy HMMA grouped GEMM: 256 thr, 2 CTA/SM ----------------
// smem: 3 stages x 32KB (Ah|Al|Bh|Bl, 8KB each) + 3 mbarriers
#define STAGE_B 32768
#define MB_OFF  (3 * STAGE_B)
#define SMEM_B  (MB_OFF + 64)

template <int G>   // 1 = gate/up + SiLU -> hbuf blocks; 2 = down -> d_acc
__global__ void __launch_bounds__(256, 2) gemm_bulk_kernel() {
    int tile = blockIdx.y;
    if (tile >= d_num_tiles) return;
    const int e = d_tile_expert[tile];
    const int row0 = d_tile_row0[tile];
    const int rowend = d_tile_rowend[tile];
    const int nb = blockIdx.x;

    extern __shared__ char smem[];
    const uint32_t sb = smem_u32(smem);
    const int tid = threadIdx.x, wid = tid >> 5, lane = tid & 31;

    const char* Ah = (const char*)((G == 1) ? d_ag_h : d_hbuf_h) + (size_t)tile * NCHUNK * BLK_B;
    const char* Al = (const char*)((G == 1) ? d_ag_l : d_hbuf_l) + (size_t)tile * NCHUNK * BLK_B;
    const char* Bh;
    const char* Bl;
    if (G == 1) {
        size_t wb = ((size_t)e * 16 + nb) * NCHUNK * BLK_B;
        Bh = (const char*)d_upwB_h + wb; Bl = (const char*)d_upwB_l + wb;
    } else {
        size_t wb = ((size_t)e * 8 + nb) * NCHUNK * BLK_B;
        Bh = (const char*)d_dnwB_h + wb; Bl = (const char*)d_dnwB_l + wb;
    }

    if (tid == 0) {
#pragma unroll
        for (int s = 0; s < 3; s++) MBAR_INIT(sb + MB_OFF + s * 8, 1);
    }
    __syncthreads();

    auto fill = [&](int s, int c) {
        uint32_t mb = sb + MB_OFF + s * 8;
        uint32_t st = sb + s * STAGE_B;
        MBAR_EXPECT_TX(mb, (uint32_t)STAGE_B);
        BULK_G2S(st,          Ah + (size_t)c * BLK_B, (uint32_t)BLK_B, mb);
        BULK_G2S(st + 8192,   Al + (size_t)c * BLK_B, (uint32_t)BLK_B, mb);
        BULK_G2S(st + 16384,  Bh + (size_t)c * BLK_B, (uint32_t)BLK_B, mb);
        BULK_G2S(st + 24576,  Bl + (size_t)c * BLK_B, (uint32_t)BLK_B, mb);
    };
    if (tid == 0) { fill(0, 0); fill(1, 1); fill(2, 2); }

    // ---- warp tiling: 4 m-warps x 2 n-warps; warp tile 32x64 ----
    const int warp_m = wid >> 1, warp_n = wid & 1;
    const int a_row = warp_m * 32 + (lane & 15);
    const uint32_t a_o0 = (uint32_t)(a_row * 64 + (lane >> 4) * 16);
    const uint32_t swm_a = (uint32_t)(((a_row >> 1) & 7) << 4);
    const int b_row = warp_n * 64 + ((lane >> 4) & 1) * 8 + (lane & 7);
    const uint32_t b_o0 = (uint32_t)(b_row * 64 + ((lane >> 3) & 1) * 16);
    const uint32_t swm_b = (uint32_t)(((b_row >> 1) & 7) << 4);

    float acc[2][8][4];
#pragma unroll
    for (int mt = 0; mt < 2; mt++)
#pragma unroll
        for (int nt = 0; nt < 8; nt++)
#pragma unroll
            for (int q = 0; q < 4; q++) acc[mt][nt][q] = 0.f;

    for (int c = 0; c < NCHUNK; c++) {
        const int s = c % 3;
        MBAR_WAIT(sb + MB_OFF + s * 8, (c / 3) & 1);
        const uint32_t st = sb + s * STAGE_B;
#pragma unroll
        for (int kb = 0; kb < 64; kb += 32) {
            uint32_t ah[2][4], al[2][4], bh[4][4], bl[4][4];
#pragma unroll
            for (int mt = 0; mt < 2; mt++) {
                uint32_t ao = (a_o0 + mt * 1024 + kb) ^ swm_a;
                LDSM_X4(ah[mt][0], ah[mt][1], ah[mt][2], ah[mt][3], st + ao);
                LDSM_X4(al[mt][0], al[mt][1], al[mt][2], al[mt][3], st + 8192 + ao);
            }
#pragma unroll
            for (int bp = 0; bp < 4; bp++) {
                // bp row offset 16 rows = 1024B; swizzle mask unchanged by +16 rows
                uint32_t bo = (b_o0 + bp * 1024 + kb) ^ swm_b;
                LDSM_X4(bh[bp][0], bh[bp][1], bh[bp][2], bh[bp][3], st + 16384 + bo);
                LDSM_X4(bl[bp][0], bl[bp][1], bl[bp][2], bl[bp][3], st + 24576 + bo);
            }
#pragma unroll
            for (int mt = 0; mt < 2; mt++)
#pragma unroll
                for (int nt = 0; nt < 8; nt++)
                    mma_bf16(acc[mt][nt], ah[mt],
                             bh[nt >> 1][(nt & 1) * 2], bh[nt >> 1][(nt & 1) * 2 + 1]);
#pragma unroll
            for (int mt = 0; mt < 2; mt++)
#pragma unroll
                for (int nt = 0; nt < 8; nt++)
                    mma_bf16(acc[mt][nt], al[mt],
                             bh[nt >> 1][(nt & 1) * 2], bh[nt >> 1][(nt & 1) * 2 + 1]);
#pragma unroll
            for (int mt = 0; mt < 2; mt++)
#pragma unroll
                for (int nt = 0; nt < 8; nt++)
                    mma_bf16(acc[mt][nt], ah[mt],
                             bl[nt >> 1][(nt & 1) * 2], bl[nt >> 1][(nt & 1) * 2 + 1]);
        }
        __syncthreads();
        if (c + 3 < NCHUNK && tid == 0) fill(s, c + 3);
    }

    // ---- epilogue ----
    if (G == 1) {
        char* hb = (char*)d_hbuf_h + (size_t)tile * NCHUNK * BLK_B;
        char* lb = (char*)d_hbuf_l + (size_t)tile * NCHUNK * BLK_B;
#pragma unroll
        for (int mt = 0; mt < 2; mt++) {
            int rA = warp_m * 32 + mt * 16 + (lane >> 2);   // local row
            int rB = rA + 8;
#pragma unroll
            for (int nt = 0; nt < 8; nt++) {
                int hc = nb * 64 + warp_n * 32 + nt * 4 + (lane & 3);   // unit col
                size_t blk = (size_t)(hc >> 5) * BLK_B;
                int coff = (hc & 31) * 2;
                float* d = acc[mt][nt];
                {
                    float g = d[0], u = d[1];
                    float h = g / (1.f + expf(-g)) * u;
                    uint32_t o = (uint32_t)(rA * 64 + coff) ^ (uint32_t)(((rA >> 1) & 7) << 4);
                    *(__nv_bfloat16*)(hb + blk + o) = __float2bfloat16(h);
                    *(__nv_bfloat16*)(lb + blk + o) = __float2bfloat16(h - bf16r(h));
                }
                {
                    float g = d[2], u = d[3];
                    float h = g / (1.f + expf(-g)) * u;
                    uint32_t o = (uint32_t)(rB * 64 + coff) ^ (uint32_t)(((rB >> 1) & 7) << 4);
                    *(__nv_bfloat16*)(hb + blk + o) = __float2bfloat16(h);
                    *(__nv_bfloat16*)(lb + blk + o) = __float2bfloat16(h - bf16r(h));
                }
            }
        }
    } else {
#pragma unroll
        for (int mt = 0; mt < 2; mt++) {
            int rA = row0 + warp_m * 32 + mt * 16 + (lane >> 2);
            int rB = rA + 8;
            if (rA < rowend) {
                int slot = d_perm[rA];
                float w = d_w_of_slot[slot];
                float* po = &d_acc[(size_t)slot * H_DIM + nb * 128 + warp_n * 64 + 2 * (lane & 3)];
#pragma unroll
                for (int nt = 0; nt < 8; nt++) {
                    float* d = acc[mt][nt];
                    *(float2*)(po + nt * 8) = make_float2(w * d[0], w * d[1]);
                }
            }
            if (rB < rowend) {
                int slot = d_perm[rB];
                float w = d_w_of_slot[slot];
                float* po = &d_acc[(size_t)slot * H_DIM + nb * 128 + warp_n * 64 + 2 * (lane & 3)];
#pragma unroll
                for (int nt = 0; nt < 8; nt++) {
                    float* d = acc[mt][nt];
                    *(float2*)(po + nt * 8) = make_float2(w * d[2], w * d[3]);
                }
            }
        }
    }
}

// ---------------- combine: out[t] = acc[2t] + acc[2t+1] ----------------
__global__ void combine_kernel(float* __restrict__ out) {
    int i = blockIdx.x * blockDim.x + threadIdx.x;
    int t = i / (H_DIM / 4);
    int c = i % (H_DIM / 4);
    const float4* a0 = (const float4*)&d_acc[(size_t)(2 * t) * H_DIM];
    const float4* a1 = (const float4*)&d_acc[(size_t)(2 * t + 1) * H_DIM];
    float4 x0 = a0[c], x1 = a1[c];
    ((float4*)out)[i] = make_float4(x0.x + x1.x, x0.y + x1.y, x0.z + x1.z, x0.w + x1.w);
}

// ---------------- launch ----------------
extern "C" void kernel_launch(void* const* d_in, const int* in_sizes, int n_in,
                              void* d_out, int out_size) {
    (void)in_sizes; (void)n_in; (void)out_size;
    const float* x      = (const float*)d_in[0];
    const float* logits = (const float*)d_in[1];
    const float* up_w   = (const float*)d_in[2];
    const float* down_w = (const float*)d_in[3];
    float* out = (float*)d_out;

    cudaFuncSetAttribute(gemm_bulk_kernel<1>, cudaFuncAttributeMaxDynamicSharedMemorySize, SMEM_B);
    cudaFuncSetAttribute(gemm_bulk_kernel<2>, cudaFuncAttributeMaxDynamicSharedMemorySize, SMEM_B);

    zero_counts_kernel<<<1, 32>>>();                                         // 0
    router_kernel<<<T_TOK / 256, 256>>>(logits);                             // 1
    setup_kernel<<<1, 256>>>();                                              // 2
    gather_a_kernel<<<dim3(NCHUNK, MAX_TILES), 128>>>(x);                    // 3
    conv_w_kernel<<<dim3(24, NCHUNK, E_NUM), 128>>>(up_w, down_w);           // 4
    gemm_bulk_kernel<1><<<dim3(16, MAX_TILES), 256, SMEM_B>>>();             // 5
    gemm_bulk_kernel<2><<<dim3(8, MAX_TILES), 256, SMEM_B>>>();              // 6
    combine_kernel<<<T_TOK * H_DIM / 4 / 256, 256>>>(out);                   // 7
}

// round 8
// speedup vs baseline: 1.9037x; 1.0091x over previous
#include <cuda_runtime.h>
#include <cuda_bf16.h>
#include <cstdint>

#define T_TOK 4096
#define H_DIM 1024
#define I_DIM 1024
#define E_NUM 8
#define S_SLOTS (T_TOK * 2)
#define BM 128
#define MAX_TILES (S_SLOTS / BM + E_NUM)   // 72
#define NCHUNK 32                          // K chunks of 32 elems (64B/row)
#define BLK_B 8192                         // one operand block: 128 rows x 64B

// ---------------- device scratch ----------------
__device__ int   d_counts[E_NUM];
__device__ int   d_expert_of_slot[S_SLOTS];
__device__ float d_w_of_slot[S_SLOTS];
__device__ int   d_perm[S_SLOTS];
__device__ int   d_tile_expert[MAX_TILES];
__device__ int   d_tile_row0[MAX_TILES];
__device__ int   d_tile_rowend[MAX_TILES];
__device__ int   d_num_tiles;

// block-chunked operands: [blockIdx][chunk] -> 8KB (128 rows x 64B, swizzled)
__device__ __align__(16) __nv_bfloat16 d_ag_h[(size_t)MAX_TILES * NCHUNK * 4096];
__device__ __align__(16) __nv_bfloat16 d_ag_l[(size_t)MAX_TILES * NCHUNK * 4096];
__device__ __align__(16) __nv_bfloat16 d_upwB_h[(size_t)E_NUM * 16 * NCHUNK * 4096];
__device__ __align__(16) __nv_bfloat16 d_upwB_l[(size_t)E_NUM * 16 * NCHUNK * 4096];
__device__ __align__(16) __nv_bfloat16 d_dnwB_h[(size_t)E_NUM * 8 * NCHUNK * 4096];
__device__ __align__(16) __nv_bfloat16 d_dnwB_l[(size_t)E_NUM * 8 * NCHUNK * 4096];
__device__ __align__(16) __nv_bfloat16 d_hbuf_h[(size_t)MAX_TILES * NCHUNK * 4096];
__device__ __align__(16) __nv_bfloat16 d_hbuf_l[(size_t)MAX_TILES * NCHUNK * 4096];

// ---------------- PTX helpers ----------------
__device__ __forceinline__ uint32_t smem_u32(const void* p) {
    uint32_t a;
    asm("{ .reg .u64 t; cvta.to.shared.u64 t, %1; cvt.u32.u64 %0, t; }" : "=r"(a) : "l"(p));
    return a;
}
#define MBAR_INIT(a, c) asm volatile("mbarrier.init.shared.b64 [%0], %1;" :: "r"(a), "r"(c) : "memory")
#define MBAR_EXPECT_TX(a, b) \
    asm volatile("mbarrier.arrive.expect_tx.shared.b64 _, [%0], %1;" :: "r"(a), "r"(b) : "memory")
#define MBAR_WAIT(a, ph) do {                                                            \
    uint32_t _m = (a), _p = (ph), _d;                                                    \
    asm volatile("{ .reg .pred p; mbarrier.try_wait.parity.acquire.cta.shared::cta.b64 " \
                 "p, [%1], %2; selp.b32 %0, 1, 0, p; }"                                  \
                 : "=r"(_d) : "r"(_m), "r"(_p) : "memory");                              \
    if (!_d) {                                                                           \
        asm volatile("{ .reg .pred P1; WL_%=: mbarrier.try_wait.parity.acquire.cta."     \
                     "shared::cta.b64 P1, [%0], %1, 0x989680; @P1 bra.uni WD_%=; "       \
                     "bra.uni WL_%=; WD_%=: }" :: "r"(_m), "r"(_p) : "memory");          \
    }                                                                                    \
} while (0)
#define BULK_G2S(dst, src, sz, mbar) \
    asm volatile("cp.async.bulk.shared::cluster.global.mbarrier::complete_tx::bytes " \
                 "[%0], [%1], %2, [%3];" :: "r"(dst), "l"(src), "r"(sz), "r"(mbar) : "memory")
#define LDSM_X4(r0, r1, r2, r3, addr) \
    asm volatile("ldmatrix.sync.aligned.m8n8.x4.shared.b16 {%0,%1,%2,%3}, [%4];" \
        : "=r"(r0), "=r"(r1), "=r"(r2), "=r"(r3) : "r"(addr))

__device__ __forceinline__ void mma_bf16(float* d, const uint32_t* a, uint32_t b0, uint32_t b1) {
    asm volatile("mma.sync.aligned.m16n8k16.row.col.f32.bf16.bf16.f32 "
        "{%0,%1,%2,%3}, {%4,%5,%6,%7}, {%8,%9}, {%0,%1,%2,%3};"
        : "+f"(d[0]), "+f"(d[1]), "+f"(d[2]), "+f"(d[3])
        : "r"(a[0]), "r"(a[1]), "r"(a[2]), "r"(a[3]), "r"(b0), "r"(b1));
}
__device__ __forceinline__ uint32_t packbf(float a, float b) {  // a->lo, b->hi
    uint32_t r;
    asm("cvt.rn.bf16x2.f32 %0, %1, %2;" : "=r"(r) : "f"(b), "f"(a));
    return r;
}
__device__ __forceinline__ float bf16r(float v) {
    return __bfloat162float(__float2bfloat16(v));
}

// split 32 fp32 -> hi/lo bf16 rows (64B each), store swizzled
__device__ __forceinline__ void store_split64(char* bh, char* bl, uint32_t off0,
                                              uint32_t swm, const float* v) {
    uint32_t hi[16], lo[16];
#pragma unroll
    for (int j = 0; j < 16; j++) {
        float a = v[2 * j], b = v[2 * j + 1];
        hi[j] = packbf(a, b);
        lo[j] = packbf(a - bf16r(a), b - bf16r(b));
    }
#pragma unroll
    for (int g = 0; g < 4; g++) {
        uint32_t o = (off0 + g * 16) ^ swm;
        *(uint4*)(bh + o) = make_uint4(hi[4 * g], hi[4 * g + 1], hi[4 * g + 2], hi[4 * g + 3]);
        *(uint4*)(bl + o) = make_uint4(lo[4 * g], lo[4 * g + 1], lo[4 * g + 2], lo[4 * g + 3]);
    }
}

// ---------------- router + sort ----------------
__global__ void zero_counts_kernel() {
    if (threadIdx.x < E_NUM) d_counts[threadIdx.x] = 0;
}
__global__ void router_kernel(const float* __restrict__ logits) {
    int t = blockIdx.x * blockDim.x + threadIdx.x;
    if (t >= T_TOK) return;
    float l[E_NUM];
#pragma unroll
    for (int e = 0; e < E_NUM; e++) l[e] = logits[t * E_NUM + e];
    int i0 = 0;
#pragma unroll
    for (int e = 1; e < E_NUM; e++) if (l[e] > l[i0]) i0 = e;
    int i1 = (i0 == 0) ? 1 : 0;
#pragma unroll
    for (int e = 0; e < E_NUM; e++) {
        if (e == i0 || e == i1) continue;
        if (l[e] > l[i1]) i1 = e;
    }
    float w0 = 1.f / (1.f + expf(l[i1] - l[i0]));
    d_expert_of_slot[2 * t] = i0; d_expert_of_slot[2 * t + 1] = i1;
    d_w_of_slot[2 * t] = w0;      d_w_of_slot[2 * t + 1] = 1.f - w0;
    atomicAdd(&d_counts[i0], 1);
    atomicAdd(&d_counts[i1], 1);
}
__global__ void setup_kernel() {
    __shared__ int s_off[E_NUM];
    __shared__ int s_cur[E_NUM];
    if (threadIdx.x == 0) {
        int acc = 0, nt = 0;
        for (int e = 0; e < E_NUM; e++) {
            int c = d_counts[e];
            s_off[e] = acc;
            for (int r = 0; r < c; r += BM) {
                d_tile_expert[nt] = e;
                d_tile_row0[nt] = acc + r;
                d_tile_rowend[nt] = acc + c;
                nt++;
            }
            acc += c;
        }
        d_num_tiles = nt;
    }
    if (threadIdx.x < E_NUM) s_cur[threadIdx.x] = 0;
    __syncthreads();
    for (int s = threadIdx.x; s < S_SLOTS; s += blockDim.x) {
        int e = d_expert_of_slot[s];
        int pos = s_off[e] + atomicAdd(&s_cur[e], 1);
        d_perm[pos] = s;
    }
}

// ---------------- prepass: gathered A blocks for GEMM1 ----------------
__global__ void gather_a_kernel(const float* __restrict__ x) {
    int tile = blockIdx.y;
    if (tile >= d_num_tiles) return;
    int c = blockIdx.x, r = threadIdx.x;
    int row0 = d_tile_row0[tile], rowend = d_tile_rowend[tile];
    size_t blk = ((size_t)tile * NCHUNK + c) * BLK_B;
    char* bh = (char*)d_ag_h + blk;
    char* bl = (char*)d_ag_l + blk;
    uint32_t off0 = r * 64, swm = ((r >> 1) & 7) << 4;
    if (row0 + r < rowend) {
        int token = d_perm[row0 + r] >> 1;
        const float4* src = (const float4*)(x + (size_t)token * H_DIM + c * 32);
        float v[32];
#pragma unroll
        for (int j = 0; j < 8; j++) {
            float4 q = src[j];
            v[4 * j] = q.x; v[4 * j + 1] = q.y; v[4 * j + 2] = q.z; v[4 * j + 3] = q.w;
        }
        store_split64(bh, bl, off0, swm, v);
    } else {
        uint4 z = make_uint4(0, 0, 0, 0);
#pragma unroll
        for (int g = 0; g < 4; g++) {
            uint32_t o = (off0 + g * 16) ^ swm;
            *(uint4*)(bh + o) = z;
            *(uint4*)(bl + o) = z;
        }
    }
}

// ---------------- prepass: weights -> block layout ----------------
__global__ void conv_w_kernel(const float* __restrict__ up_w,
                              const float* __restrict__ dn_w) {
    int e = blockIdx.z, c = blockIdx.y, bx = blockIdx.x, r = threadIdx.x;
    const float* src;
    char *bh, *bl;
    int N, ncol;
    if (bx < 16) {
        N = 2 * I_DIM;
        src = up_w + (size_t)e * H_DIM * N;
        int u = bx * 64 + (r >> 1);
        ncol = (r & 1) ? I_DIM + u : u;
        size_t blk = (((size_t)e * 16 + bx) * NCHUNK + c) * BLK_B;
        bh = (char*)d_upwB_h + blk; bl = (char*)d_upwB_l + blk;
    } else {
        N = H_DIM;
        src = dn_w + (size_t)e * I_DIM * N;
        ncol = (bx - 16) * 128 + r;
        size_t blk = (((size_t)e * 8 + (bx - 16)) * NCHUNK + c) * BLK_B;
        bh = (char*)d_dnwB_h + blk; bl = (char*)d_dnwB_l + blk;
    }
    float v[32];
#pragma unroll
    for (int j = 0; j < 32; j++) v[j] = src[(size_t)(c * 32 + j) * N + ncol];
    store_split64(bh, bl, r * 64, ((r >> 1) & 7) << 4, v);
}

// ---------------- zero output (out is poisoned by harness) ----------------
__global__ void zero_out_kernel(float* __restrict__ out) {
    int i = blockIdx.x * blockDim.x + threadIdx.x;
    ((float4*)out)[i] = make_float4(0.f, 0.f, 0.f, 0.f);
}

// ---------------- bulk-copy HMMA grouped GEMM: 128 thr (4 warps 64x64), 2 CTA/SM
#define STAGE_B 32768
#define MB_OFF  (3 * STAGE_B)
#define SMEM_B  (MB_OFF + 64)

template <int G>   // 1 = gate/up + SiLU -> hbuf blocks; 2 = down -> atomic out
__global__ void __launch_bounds__(128, 2) gemm_bulk_kernel(float* __restrict__ out) {
    int tile = blockIdx.y;
    if (tile >= d_num_tiles) return;
    const int e = d_tile_expert[tile];
    const int row0 = d_tile_row0[tile];
    const int rowend = d_tile_rowend[tile];
    const int nb = blockIdx.x;

    extern __shared__ char smem[];
    const uint32_t sb = smem_u32(smem);
    const int tid = threadIdx.x, wid = tid >> 5, lane = tid & 31;

    const char* Ah = (const char*)((G == 1) ? d_ag_h : d_hbuf_h) + (size_t)tile * NCHUNK * BLK_B;
    const char* Al = (const char*)((G == 1) ? d_ag_l : d_hbuf_l) + (size_t)tile * NCHUNK * BLK_B;
    const char* Bh;
    const char* Bl;
    if (G == 1) {
        size_t wb = ((size_t)e * 16 + nb) * NCHUNK * BLK_B;
        Bh = (const char*)d_upwB_h + wb; Bl = (const char*)d_upwB_l + wb;
    } else {
        size_t wb = ((size_t)e * 8 + nb) * NCHUNK * BLK_B;
        Bh = (const char*)d_dnwB_h + wb; Bl = (const char*)d_dnwB_l + wb;
    }

    if (tid == 0) {
#pragma unroll
        for (int s = 0; s < 3; s++) MBAR_INIT(sb + MB_OFF + s * 8, 1);
    }
    __syncthreads();

    auto fill = [&](int s, int c) {
        uint32_t mb = sb + MB_OFF + s * 8;
        uint32_t st = sb + s * STAGE_B;
        MBAR_EXPECT_TX(mb, (uint32_t)STAGE_B);
        BULK_G2S(st,          Ah + (size_t)c * BLK_B, (uint32_t)BLK_B, mb);
        BULK_G2S(st + 8192,   Al + (size_t)c * BLK_B, (uint32_t)BLK_B, mb);
        BULK_G2S(st + 16384,  Bh + (size_t)c * BLK_B, (uint32_t)BLK_B, mb);
        BULK_G2S(st + 24576,  Bl + (size_t)c * BLK_B, (uint32_t)BLK_B, mb);
    };
    if (tid == 0) { fill(0, 0); fill(1, 1); fill(2, 2); }

    // ---- warp tiling: 2 m-warps x 2 n-warps; warp tile 64x64 ----
    const int warp_m = wid >> 1, warp_n = wid & 1;
    const int a_row = warp_m * 64 + (lane & 15);
    const uint32_t a_o0 = (uint32_t)(a_row * 64 + (lane >> 4) * 16);
    const uint32_t swm_a = (uint32_t)(((a_row >> 1) & 7) << 4);
    const int b_row = warp_n * 64 + ((lane >> 4) & 1) * 8 + (lane & 7);
    const uint32_t b_o0 = (uint32_t)(b_row * 64 + ((lane >> 3) & 1) * 16);
    const uint32_t swm_b = (uint32_t)(((b_row >> 1) & 7) << 4);

    float acc[4][8][4];
#pragma unroll
    for (int mt = 0; mt < 4; mt++)
#pragma unroll
        for (int nt = 0; nt < 8; nt++)
#pragma unroll
            for (int q = 0; q < 4; q++) acc[mt][nt][q] = 0.f;

    for (int c = 0; c < NCHUNK; c++) {
        const int s = c % 3;
        MBAR_WAIT(sb + MB_OFF + s * 8, (c / 3) & 1);
        const uint32_t st = sb + s * STAGE_B;
#pragma unroll
        for (int kb = 0; kb < 64; kb += 32) {
            uint32_t ah[4][4], al[4][4], bh[4][4], bl[4][4];
#pragma unroll
            for (int mt = 0; mt < 4; mt++) {
                // +16 rows = +1024B; (row>>1)&7 invariant under +16 rows
                uint32_t ao = (a_o0 + mt * 1024 + kb) ^ swm_a;
                LDSM_X4(ah[mt][0], ah[mt][1], ah[mt][2], ah[mt][3], st + ao);
                LDSM_X4(al[mt][0], al[mt][1], al[mt][2], al[mt][3], st + 8192 + ao);
            }
#pragma unroll
            for (int bp = 0; bp < 4; bp++) {
                uint32_t bo = (b_o0 + bp * 1024 + kb) ^ swm_b;
                LDSM_X4(bh[bp][0], bh[bp][1], bh[bp][2], bh[bp][3], st + 16384 + bo);
                LDSM_X4(bl[bp][0], bl[bp][1], bl[bp][2], bl[bp][3], st + 24576 + bo);
            }
#pragma unroll
            for (int mt = 0; mt < 4; mt++)
#pragma unroll
                for (int nt = 0; nt < 8; nt++)
                    mma_bf16(acc[mt][nt], ah[mt],
                             bh[nt >> 1][(nt & 1) * 2], bh[nt >> 1][(nt & 1) * 2 + 1]);
#pragma unroll
            for (int mt = 0; mt < 4; mt++)
#pragma unroll
                for (int nt = 0; nt < 8; nt++)
                    mma_bf16(acc[mt][nt], al[mt],
                             bh[nt >> 1][(nt & 1) * 2], bh[nt >> 1][(nt & 1) * 2 + 1]);
#pragma unroll
            for (int mt = 0; mt < 4; mt++)
#pragma unroll
                for (int nt = 0; nt < 8; nt++)
                    mma_bf16(acc[mt][nt], ah[mt],
                             bl[nt >> 1][(nt & 1) * 2], bl[nt >> 1][(nt & 1) * 2 + 1]);
        }
        __syncthreads();
        if (c + 3 < NCHUNK && tid == 0) fill(s, c + 3);
    }

    // ---- epilogue ----
    if (G == 1) {
        char* hb = (char*)d_hbuf_h + (size_t)tile * NCHUNK * BLK_B;
        char* lb = (char*)d_hbuf_l + (size_t)tile * NCHUNK * BLK_B;
#pragma unroll
        for (int mt = 0; mt < 4; mt++) {
            int rA = warp_m * 64 + mt * 16 + (lane >> 2);   // local row
            int rB = rA + 8;
#pragma unroll
            for (int nt = 0; nt < 8; nt++) {
                int hc = nb * 64 + warp_n * 32 + nt * 4 + (lane & 3);   // unit col
                size_t blk = (size_t)(hc >> 5) * BLK_B;
                int coff = (hc & 31) * 2;
                float* d = acc[mt][nt];
                {
                    float g = d[0], u = d[1];
                    float h = g / (1.f + expf(-g)) * u;
                    uint32_t o = (uint32_t)(rA * 64 + coff) ^ (uint32_t)(((rA >> 1) & 7) << 4);
                    *(__nv_bfloat16*)(hb + blk + o) = __float2bfloat16(h);
                    *(__nv_bfloat16*)(lb + blk + o) = __float2bfloat16(h - bf16r(h));
                }
                {
                    float g = d[2], u = d[3];
                    float h = g / (1.f + expf(-g)) * u;
                    uint32_t o = (uint32_t)(rB * 64 + coff) ^ (uint32_t)(((rB >> 1) & 7) << 4);
                    *(__nv_bfloat16*)(hb + blk + o) = __float2bfloat16(h);
                    *(__nv_bfloat16*)(lb + blk + o) = __float2bfloat16(h - bf16r(h));
                }
            }
        }
    } else {
        // scatter w*acc directly into out; exactly 2 commutative adds/element
#pragma unroll
        for (int mt = 0; mt < 4; mt++) {
            int rA = row0 + warp_m * 64 + mt * 16 + (lane >> 2);
            int rB = rA + 8;
            if (rA < rowend) {
                int slot = d_perm[rA];
                float w = d_w_of_slot[slot];
                float* po = out + (size_t)(slot >> 1) * H_DIM + nb * 128 + warp_n * 64 + 2 * (lane & 3);
#pragma unroll
                for (int nt = 0; nt < 8; nt++) {
                    float* d = acc[mt][nt];
                    atomicAdd(po + nt * 8,     w * d[0]);
                    atomicAdd(po + nt * 8 + 1, w * d[1]);
                }
            }
            if (rB < rowend) {
                int slot = d_perm[rB];
                float w = d_w_of_slot[slot];
                float* po = out + (size_t)(slot >> 1) * H_DIM + nb * 128 + warp_n * 64 + 2 * (lane & 3);
#pragma unroll
                for (int nt = 0; nt < 8; nt++) {
                    float* d = acc[mt][nt];
                    atomicAdd(po + nt * 8,     w * d[2]);
                    atomicAdd(po + nt * 8 + 1, w * d[3]);
                }
            }
        }
    }
}

// ---------------- launch ----------------
extern "C" void kernel_launch(void* const* d_in, const int* in_sizes, int n_in,
                              void* d_out, int out_size) {
    (void)in_sizes; (void)n_in; (void)out_size;
    const float* x      = (const float*)d_in[0];
    const float* logits = (const float*)d_in[1];
    const float* up_w   = (const float*)d_in[2];
    const float* down_w = (const float*)d_in[3];
    float* out = (float*)d_out;

    cudaFuncSetAttribute(gemm_bulk_kernel<1>, cudaFuncAttributeMaxDynamicSharedMemorySize, SMEM_B);
    cudaFuncSetAttribute(gemm_bulk_kernel<2>, cudaFuncAttributeMaxDynamicSharedMemorySize, SMEM_B);

    zero_counts_kernel<<<1, 32>>>();                                         // 0
    router_kernel<<<T_TOK / 256, 256>>>(logits);                             // 1
    setup_kernel<<<1, 256>>>();                                              // 2
    zero_out_kernel<<<T_TOK * H_DIM / 4 / 256, 256>>>(out);                  // 3
    gather_a_kernel<<<dim3(NCHUNK, MAX_TILES), 128>>>(x);                    // 4
    conv_w_kernel<<<dim3(24, NCHUNK, E_NUM), 128>>>(up_w, down_w);           // 5
    gemm_bulk_kernel<1><<<dim3(16, MAX_TILES), 128, SMEM_B>>>(nullptr);      // 6
    gemm_bulk_kernel<2><<<dim3(8, MAX_TILES), 128, SMEM_B>>>(out);           // 7
}

// round 9
// speedup vs baseline: 1.9253x; 1.0113x over previous
#include <cuda_runtime.h>
#include <cuda_bf16.h>
#include <cstdint>

#define T_TOK 4096
#define H_DIM 1024
#define I_DIM 1024
#define E_NUM 8
#define S_SLOTS (T_TOK * 2)
#define BM 128
#define MAX_TILES (S_SLOTS / BM + E_NUM)   // 72
#define NCHUNK 32                          // K chunks of 32 elems (64B/row)
#define BLK_B 8192                         // one operand block: 128 rows x 64B

// ---------------- device scratch ----------------
__device__ int   d_counts[E_NUM];
__device__ int   d_expert_of_slot[S_SLOTS];
__device__ float d_w_of_slot[S_SLOTS];
__device__ int   d_perm[S_SLOTS];
__device__ int   d_tile_expert[MAX_TILES];
__device__ int   d_tile_row0[MAX_TILES];
__device__ int   d_tile_rowend[MAX_TILES];
__device__ int   d_num_tiles;

// block-chunked operands: [blockIdx][chunk] -> 8KB (128 rows x 64B, swizzled)
__device__ __align__(16) __nv_bfloat16 d_ag_h[(size_t)MAX_TILES * NCHUNK * 4096];
__device__ __align__(16) __nv_bfloat16 d_ag_l[(size_t)MAX_TILES * NCHUNK * 4096];
__device__ __align__(16) __nv_bfloat16 d_upwB_h[(size_t)E_NUM * 16 * NCHUNK * 4096];
__device__ __align__(16) __nv_bfloat16 d_upwB_l[(size_t)E_NUM * 16 * NCHUNK * 4096];
__device__ __align__(16) __nv_bfloat16 d_dnwB_h[(size_t)E_NUM * 8 * NCHUNK * 4096];
__device__ __align__(16) __nv_bfloat16 d_dnwB_l[(size_t)E_NUM * 8 * NCHUNK * 4096];
__device__ __align__(16) __nv_bfloat16 d_hbuf_h[(size_t)MAX_TILES * NCHUNK * 4096];
__device__ __align__(16) __nv_bfloat16 d_hbuf_l[(size_t)MAX_TILES * NCHUNK * 4096];

// ---------------- PTX helpers ----------------
__device__ __forceinline__ uint32_t smem_u32(const void* p) {
    uint32_t a;
    asm("{ .reg .u64 t; cvta.to.shared.u64 t, %1; cvt.u32.u64 %0, t; }" : "=r"(a) : "l"(p));
    return a;
}
#define MBAR_INIT(a, c) asm volatile("mbarrier.init.shared.b64 [%0], %1;" :: "r"(a), "r"(c) : "memory")
#define MBAR_EXPECT_TX(a, b) \
    asm volatile("mbarrier.arrive.expect_tx.shared.b64 _, [%0], %1;" :: "r"(a), "r"(b) : "memory")
#define MBAR_WAIT(a, ph) do {                                                            \
    uint32_t _m = (a), _p = (ph), _d;                                                    \
    asm volatile("{ .reg .pred p; mbarrier.try_wait.parity.acquire.cta.shared::cta.b64 " \
                 "p, [%1], %2; selp.b32 %0, 1, 0, p; }"                                  \
                 : "=r"(_d) : "r"(_m), "r"(_p) : "memory");                              \
    if (!_d) {                                                                           \
        asm volatile("{ .reg .pred P1; WL_%=: mbarrier.try_wait.parity.acquire.cta."     \
                     "shared::cta.b64 P1, [%0], %1, 0x989680; @P1 bra.uni WD_%=; "       \
                     "bra.uni WL_%=; WD_%=: }" :: "r"(_m), "r"(_p) : "memory");          \
    }                                                                                    \
} while (0)
#define BULK_G2S(dst, src, sz, mbar) \
    asm volatile("cp.async.bulk.shared::cluster.global.mbarrier::complete_tx::bytes " \
                 "[%0], [%1], %2, [%3];" :: "r"(dst), "l"(src), "r"(sz), "r"(mbar) : "memory")
#define LDSM_X4(r0, r1, r2, r3, addr) \
    asm volatile("ldmatrix.sync.aligned.m8n8.x4.shared.b16 {%0,%1,%2,%3}, [%4];" \
        : "=r"(r0), "=r"(r1), "=r"(r2), "=r"(r3) : "r"(addr))

__device__ __forceinline__ void mma_bf16(float* d, const uint32_t* a, uint32_t b0, uint32_t b1) {
    asm volatile("mma.sync.aligned.m16n8k16.row.col.f32.bf16.bf16.f32 "
        "{%0,%1,%2,%3}, {%4,%5,%6,%7}, {%8,%9}, {%0,%1,%2,%3};"
        : "+f"(d[0]), "+f"(d[1]), "+f"(d[2]), "+f"(d[3])
        : "r"(a[0]), "r"(a[1]), "r"(a[2]), "r"(a[3]), "r"(b0), "r"(b1));
}
__device__ __forceinline__ uint32_t packbf(float a, float b) {  // a->lo, b->hi
    uint32_t r;
    asm("cvt.rn.bf16x2.f32 %0, %1, %2;" : "=r"(r) : "f"(b), "f"(a));
    return r;
}
__device__ __forceinline__ float bf16r(float v) {
    return __bfloat162float(__float2bfloat16(v));
}

// split 32 fp32 -> hi/lo bf16 rows (64B each), store swizzled
__device__ __forceinline__ void store_split64(char* bh, char* bl, uint32_t off0,
                                              uint32_t swm, const float* v) {
    uint32_t hi[16], lo[16];
#pragma unroll
    for (int j = 0; j < 16; j++) {
        float a = v[2 * j], b = v[2 * j + 1];
        hi[j] = packbf(a, b);
        lo[j] = packbf(a - bf16r(a), b - bf16r(b));
    }
#pragma unroll
    for (int g = 0; g < 4; g++) {
        uint32_t o = (off0 + g * 16) ^ swm;
        *(uint4*)(bh + o) = make_uint4(hi[4 * g], hi[4 * g + 1], hi[4 * g + 2], hi[4 * g + 3]);
        *(uint4*)(bl + o) = make_uint4(lo[4 * g], lo[4 * g + 1], lo[4 * g + 2], lo[4 * g + 3]);
    }
}

// ---------------- router + sort ----------------
__global__ void zero_counts_kernel() {
    if (threadIdx.x < E_NUM) d_counts[threadIdx.x] = 0;
}
__global__ void router_kernel(const float* __restrict__ logits) {
    int t = blockIdx.x * blockDim.x + threadIdx.x;
    if (t >= T_TOK) return;
    float l[E_NUM];
#pragma unroll
    for (int e = 0; e < E_NUM; e++) l[e] = logits[t * E_NUM + e];
    int i0 = 0;
#pragma unroll
    for (int e = 1; e < E_NUM; e++) if (l[e] > l[i0]) i0 = e;
    int i1 = (i0 == 0) ? 1 : 0;
#pragma unroll
    for (int e = 0; e < E_NUM; e++) {
        if (e == i0 || e == i1) continue;
        if (l[e] > l[i1]) i1 = e;
    }
    float w0 = 1.f / (1.f + expf(l[i1] - l[i0]));
    d_expert_of_slot[2 * t] = i0; d_expert_of_slot[2 * t + 1] = i1;
    d_w_of_slot[2 * t] = w0;      d_w_of_slot[2 * t + 1] = 1.f - w0;
    atomicAdd(&d_counts[i0], 1);
    atomicAdd(&d_counts[i1], 1);
}
__global__ void setup_kernel() {
    __shared__ int s_off[E_NUM];
    __shared__ int s_cur[E_NUM];
    if (threadIdx.x == 0) {
        int acc = 0, nt = 0;
        for (int e = 0; e < E_NUM; e++) {
            int c = d_counts[e];
            s_off[e] = acc;
            for (int r = 0; r < c; r += BM) {
                d_tile_expert[nt] = e;
                d_tile_row0[nt] = acc + r;
                d_tile_rowend[nt] = acc + c;
                nt++;
            }
            acc += c;
        }
        d_num_tiles = nt;
    }
    if (threadIdx.x < E_NUM) s_cur[threadIdx.x] = 0;
    __syncthreads();
    for (int s = threadIdx.x; s < S_SLOTS; s += blockDim.x) {
        int e = d_expert_of_slot[s];
        int pos = s_off[e] + atomicAdd(&s_cur[e], 1);
        d_perm[pos] = s;
    }
}

// ---------------- merged prepass: gather_a + conv_w + zero_out in ONE launch ----
// flat grid segments: [0,2304) gather A; [2304,8448) weights; [8448,10496) zero out
#define G_A_BLKS (NCHUNK * MAX_TILES)        // 2304
#define G_W_BLKS (24 * NCHUNK * E_NUM)       // 6144
#define G_Z_BLKS 2048
#define G_TOTAL  (G_A_BLKS + G_W_BLKS + G_Z_BLKS)   // 10496

__global__ void __launch_bounds__(128) prepass_kernel(const float* __restrict__ x,
                                                      const float* __restrict__ up_w,
                                                      const float* __restrict__ dn_w,
                                                      float* __restrict__ out) {
    const int b = blockIdx.x, tid = threadIdx.x;
    if (b < G_A_BLKS) {
        // ---- gather A blocks (latency-bound; overlaps with weight conversion) ----
        int tile = b >> 5;                 // b / NCHUNK
        if (tile >= d_num_tiles) return;
        int c = b & 31;
        int r = tid;
        int row0 = d_tile_row0[tile], rowend = d_tile_rowend[tile];
        size_t blk = ((size_t)tile * NCHUNK + c) * BLK_B;
        char* bh = (char*)d_ag_h + blk;
        char* bl = (char*)d_ag_l + blk;
        uint32_t off0 = r * 64, swm = ((r >> 1) & 7) << 4;
        if (row0 + r < rowend) {
            int token = d_perm[row0 + r] >> 1;
            const float4* src = (const float4*)(x + (size_t)token * H_DIM + c * 32);
            float v[32];
#pragma unroll
            for (int j = 0; j < 8; j++) {
                float4 q = src[j];
                v[4 * j] = q.x; v[4 * j + 1] = q.y; v[4 * j + 2] = q.z; v[4 * j + 3] = q.w;
            }
            store_split64(bh, bl, off0, swm, v);
        } else {
            uint4 z = make_uint4(0, 0, 0, 0);
#pragma unroll
            for (int g = 0; g < 4; g++) {
                uint32_t o = (off0 + g * 16) ^ swm;
                *(uint4*)(bh + o) = z;
                *(uint4*)(bl + o) = z;
            }
        }
    } else if (b < G_A_BLKS + G_W_BLKS) {
        // ---- weights -> block layout ----
        int rem = b - G_A_BLKS;
        int e = rem / (24 * NCHUNK);
        int r2 = rem % (24 * NCHUNK);
        int c = r2 / 24;
        int bx = r2 % 24;
        int r = tid;
        const float* src;
        char *bh, *bl;
        int N, ncol;
        if (bx < 16) {
            N = 2 * I_DIM;
            src = up_w + (size_t)e * H_DIM * N;
            int u = bx * 64 + (r >> 1);
            ncol = (r & 1) ? I_DIM + u : u;
            size_t blk = (((size_t)e * 16 + bx) * NCHUNK + c) * BLK_B;
            bh = (char*)d_upwB_h + blk; bl = (char*)d_upwB_l + blk;
        } else {
            N = H_DIM;
            src = dn_w + (size_t)e * I_DIM * N;
            ncol = (bx - 16) * 128 + r;
            size_t blk = (((size_t)e * 8 + (bx - 16)) * NCHUNK + c) * BLK_B;
            bh = (char*)d_dnwB_h + blk; bl = (char*)d_dnwB_l + blk;
        }
        float v[32];
#pragma unroll
        for (int j = 0; j < 32; j++) v[j] = src[(size_t)(c * 32 + j) * N + ncol];
        store_split64(bh, bl, r * 64, ((r >> 1) & 7) << 4, v);
    } else {
        // ---- zero out (poisoned by harness); 4 float4 per thread ----
        size_t i0 = ((size_t)(b - G_A_BLKS - G_W_BLKS) * 128 + tid) * 4;
        float4* o = (float4*)out;
        float4 z = make_float4(0.f, 0.f, 0.f, 0.f);
#pragma unroll
        for (int j = 0; j < 4; j++) o[i0 + j] = z;
    }
}

// ---------------- bulk-copy HMMA grouped GEMM: 128 thr (4 warps 64x64), 2 CTA/SM
#define STAGE_B 32768
#define MB_OFF  (3 * STAGE_B)
#define SMEM_B  (MB_OFF + 64)

template <int G>   // 1 = gate/up + SiLU -> hbuf blocks; 2 = down -> atomic out
__global__ void __launch_bounds__(128, 2) gemm_bulk_kernel(float* __restrict__ out) {
    int tile = blockIdx.y;
    if (tile >= d_num_tiles) return;
    const int e = d_tile_expert[tile];
    const int row0 = d_tile_row0[tile];
    const int rowend = d_tile_rowend[tile];
    const int nb = blockIdx.x;

    extern __shared__ char smem[];
    const uint32_t sb = smem_u32(smem);
    const int tid = threadIdx.x, wid = tid >> 5, lane = tid & 31;

    const char* Ah = (const char*)((G == 1) ? d_ag_h : d_hbuf_h) + (size_t)tile * NCHUNK * BLK_B;
    const char* Al = (const char*)((G == 1) ? d_ag_l : d_hbuf_l) + (size_t)tile * NCHUNK * BLK_B;
    const char* Bh;
    const char* Bl;
    if (G == 1) {
        size_t wb = ((size_t)e * 16 + nb) * NCHUNK * BLK_B;
        Bh = (const char*)d_upwB_h + wb; Bl = (const char*)d_upwB_l + wb;
    } else {
        size_t wb = ((size_t)e * 8 + nb) * NCHUNK * BLK_B;
        Bh = (const char*)d_dnwB_h + wb; Bl = (const char*)d_dnwB_l + wb;
    }

    if (tid == 0) {
#pragma unroll
        for (int s = 0; s < 3; s++) MBAR_INIT(sb + MB_OFF + s * 8, 1);
    }
    __syncthreads();

    auto fill = [&](int s, int c) {
        uint32_t mb = sb + MB_OFF + s * 8;
        uint32_t st = sb + s * STAGE_B;
        MBAR_EXPECT_TX(mb, (uint32_t)STAGE_B);
        BULK_G2S(st,          Ah + (size_t)c * BLK_B, (uint32_t)BLK_B, mb);
        BULK_G2S(st + 8192,   Al + (size_t)c * BLK_B, (uint32_t)BLK_B, mb);
        BULK_G2S(st + 16384,  Bh + (size_t)c * BLK_B, (uint32_t)BLK_B, mb);
        BULK_G2S(st + 24576,  Bl + (size_t)c * BLK_B, (uint32_t)BLK_B, mb);
    };
    if (tid == 0) { fill(0, 0); fill(1, 1); fill(2, 2); }

    // ---- warp tiling: 2 m-warps x 2 n-warps; warp tile 64x64 ----
    const int warp_m = wid >> 1, warp_n = wid & 1;
    const int a_row = warp_m * 64 + (lane & 15);
    const uint32_t a_o0 = (uint32_t)(a_row * 64 + (lane >> 4) * 16);
    const uint32_t swm_a = (uint32_t)(((a_row >> 1) & 7) << 4);
    const int b_row = warp_n * 64 + ((lane >> 4) & 1) * 8 + (lane & 7);
    const uint32_t b_o0 = (uint32_t)(b_row * 64 + ((lane >> 3) & 1) * 16);
    const uint32_t swm_b = (uint32_t)(((b_row >> 1) & 7) << 4);

    float acc[4][8][4];
#pragma unroll
    for (int mt = 0; mt < 4; mt++)
#pragma unroll
        for (int nt = 0; nt < 8; nt++)
#pragma unroll
            for (int q = 0; q < 4; q++) acc[mt][nt][q] = 0.f;

    for (int c = 0; c < NCHUNK; c++) {
        const int s = c % 3;
        MBAR_WAIT(sb + MB_OFF + s * 8, (c / 3) & 1);
        const uint32_t st = sb + s * STAGE_B;
#pragma unroll
        for (int kb = 0; kb < 64; kb += 32) {
            uint32_t ah[4][4], al[4][4], bh[4][4], bl[4][4];
#pragma unroll
            for (int mt = 0; mt < 4; mt++) {
                uint32_t ao = (a_o0 + mt * 1024 + kb) ^ swm_a;
                LDSM_X4(ah[mt][0], ah[mt][1], ah[mt][2], ah[mt][3], st + ao);
                LDSM_X4(al[mt][0], al[mt][1], al[mt][2], al[mt][3], st + 8192 + ao);
            }
#pragma unroll
            for (int bp = 0; bp < 4; bp++) {
                uint32_t bo = (b_o0 + bp * 1024 + kb) ^ swm_b;
                LDSM_X4(bh[bp][0], bh[bp][1], bh[bp][2], bh[bp][3], st + 16384 + bo);
                LDSM_X4(bl[bp][0], bl[bp][1], bl[bp][2], bl[bp][3], st + 24576 + bo);
            }
#pragma unroll
            for (int mt = 0; mt < 4; mt++)
#pragma unroll
                for (int nt = 0; nt < 8; nt++)
                    mma_bf16(acc[mt][nt], ah[mt],
                             bh[nt >> 1][(nt & 1) * 2], bh[nt >> 1][(nt & 1) * 2 + 1]);
#pragma unroll
            for (int mt = 0; mt < 4; mt++)
#pragma unroll
                for (int nt = 0; nt < 8; nt++)
                    mma_bf16(acc[mt][nt], al[mt],
                             bh[nt >> 1][(nt & 1) * 2], bh[nt >> 1][(nt & 1) * 2 + 1]);
#pragma unroll
            for (int mt = 0; mt < 4; mt++)
#pragma unroll
                for (int nt = 0; nt < 8; nt++)
                    mma_bf16(acc[mt][nt], ah[mt],
                             bl[nt >> 1][(nt & 1) * 2], bl[nt >> 1][(nt & 1) * 2 + 1]);
        }
        __syncthreads();
        if (c + 3 < NCHUNK && tid == 0) fill(s, c + 3);
    }

    // ---- epilogue ----
    if (G == 1) {
        char* hb = (char*)d_hbuf_h + (size_t)tile * NCHUNK * BLK_B;
        char* lb = (char*)d_hbuf_l + (size_t)tile * NCHUNK * BLK_B;
#pragma unroll
        for (int mt = 0; mt < 4; mt++) {
            int rA = warp_m * 64 + mt * 16 + (lane >> 2);   // local row
            int rB = rA + 8;
#pragma unroll
            for (int nt = 0; nt < 8; nt++) {
                int hc = nb * 64 + warp_n * 32 + nt * 4 + (lane & 3);   // unit col
                size_t blk = (size_t)(hc >> 5) * BLK_B;
                int coff = (hc & 31) * 2;
                float* d = acc[mt][nt];
                {
                    float g = d[0], u = d[1];
                    float h = g / (1.f + expf(-g)) * u;
                    uint32_t o = (uint32_t)(rA * 64 + coff) ^ (uint32_t)(((rA >> 1) & 7) << 4);
                    *(__nv_bfloat16*)(hb + blk + o) = __float2bfloat16(h);
                    *(__nv_bfloat16*)(lb + blk + o) = __float2bfloat16(h - bf16r(h));
                }
                {
                    float g = d[2], u = d[3];
                    float h = g / (1.f + expf(-g)) * u;
                    uint32_t o = (uint32_t)(rB * 64 + coff) ^ (uint32_t)(((rB >> 1) & 7) << 4);
                    *(__nv_bfloat16*)(hb + blk + o) = __float2bfloat16(h);
                    *(__nv_bfloat16*)(lb + blk + o) = __float2bfloat16(h - bf16r(h));
                }
            }
        }
    } else {
        // scatter w*acc directly into out; exactly 2 commutative adds/element
#pragma unroll
        for (int mt = 0; mt < 4; mt++) {
            int rA = row0 + warp_m * 64 + mt * 16 + (lane >> 2);
            int rB = rA + 8;
            if (rA < rowend) {
                int slot = d_perm[rA];
                float w = d_w_of_slot[slot];
                float* po = out + (size_t)(slot >> 1) * H_DIM + nb * 128 + warp_n * 64 + 2 * (lane & 3);
#pragma unroll
                for (int nt = 0; nt < 8; nt++) {
                    float* d = acc[mt][nt];
                    atomicAdd(po + nt * 8,     w * d[0]);
                    atomicAdd(po + nt * 8 + 1, w * d[1]);
                }
            }
            if (rB < rowend) {
                int slot = d_perm[rB];
                float w = d_w_of_slot[slot];
                float* po = out + (size_t)(slot >> 1) * H_DIM + nb * 128 + warp_n * 64 + 2 * (lane & 3);
#pragma unroll
                for (int nt = 0; nt < 8; nt++) {
                    float* d = acc[mt][nt];
                    atomicAdd(po + nt * 8,     w * d[2]);
                    atomicAdd(po + nt * 8 + 1, w * d[3]);
                }
            }
        }
    }
}

// ---------------- launch ----------------
extern "C" void kernel_launch(void* const* d_in, const int* in_sizes, int n_in,
                              void* d_out, int out_size) {
    (void)in_sizes; (void)n_in; (void)out_size;
    const float* x      = (const float*)d_in[0];
    const float* logits = (const float*)d_in[1];
    const float* up_w   = (const float*)d_in[2];
    const float* down_w = (const float*)d_in[3];
    float* out = (float*)d_out;

    cudaFuncSetAttribute(gemm_bulk_kernel<1>, cudaFuncAttributeMaxDynamicSharedMemorySize, SMEM_B);
    cudaFuncSetAttribute(gemm_bulk_kernel<2>, cudaFuncAttributeMaxDynamicSharedMemorySize, SMEM_B);

    zero_counts_kernel<<<1, 32>>>();                                         // 0
    router_kernel<<<T_TOK / 256, 256>>>(logits);                             // 1
    setup_kernel<<<1, 256>>>();                                              // 2
    prepass_kernel<<<G_TOTAL, 128>>>(x, up_w, down_w, out);                  // 3 (merged)
    gemm_bulk_kernel<1><<<dim3(16, MAX_TILES), 128, SMEM_B>>>(nullptr);      // 4
    gemm_bulk_kernel<2><<<dim3(8, MAX_TILES), 128, SMEM_B>>>(out);           // 5
}

// round 11
// speedup vs baseline: 2.0432x; 1.0613x over previous
#include <cuda_runtime.h>
#include <cuda_bf16.h>
#include <cstdint>

#define T_TOK 4096
#define H_DIM 1024
#define I_DIM 1024
#define E_NUM 8
#define S_SLOTS (T_TOK * 2)
#define BM 128
#define MAX_TILES (S_SLOTS / BM + E_NUM)   // 72
#define NCHUNK 32                          // K chunks of 32 elems (64B/row)
#define BLK_B 8192                         // one operand block: 128 rows x 64B

// ---------------- device scratch ----------------
__device__ int   d_counts[E_NUM];
__device__ int   d_expert_of_slot[S_SLOTS];
__device__ float d_w_of_slot[S_SLOTS];
__device__ int   d_perm[S_SLOTS];
__device__ int   d_tile_expert[MAX_TILES];
__device__ int   d_tile_row0[MAX_TILES];
__device__ int   d_tile_rowend[MAX_TILES];
__device__ int   d_num_tiles;
__device__ int   d_tile_flags[MAX_TILES];   // GEMM1 blocks done per tile

// block-chunked operands: [blockIdx][chunk] -> 8KB (128 rows x 64B, swizzled)
__device__ __align__(16) __nv_bfloat16 d_ag_h[(size_t)MAX_TILES * NCHUNK * 4096];
__device__ __align__(16) __nv_bfloat16 d_ag_l[(size_t)MAX_TILES * NCHUNK * 4096];
__device__ __align__(16) __nv_bfloat16 d_upwB_h[(size_t)E_NUM * 16 * NCHUNK * 4096];
__device__ __align__(16) __nv_bfloat16 d_upwB_l[(size_t)E_NUM * 16 * NCHUNK * 4096];
__device__ __align__(16) __nv_bfloat16 d_dnwB_h[(size_t)E_NUM * 8 * NCHUNK * 4096];
__device__ __align__(16) __nv_bfloat16 d_dnwB_l[(size_t)E_NUM * 8 * NCHUNK * 4096];
__device__ __align__(16) __nv_bfloat16 d_hbuf_h[(size_t)MAX_TILES * NCHUNK * 4096];
__device__ __align__(16) __nv_bfloat16 d_hbuf_l[(size_t)MAX_TILES * NCHUNK * 4096];

// ---------------- PTX helpers ----------------
__device__ __forceinline__ uint32_t smem_u32(const void* p) {
    uint32_t a;
    asm("{ .reg .u64 t; cvta.to.shared.u64 t, %1; cvt.u32.u64 %0, t; }" : "=r"(a) : "l"(p));
    return a;
}
#define MBAR_INIT(a, c) asm volatile("mbarrier.init.shared.b64 [%0], %1;" :: "r"(a), "r"(c) : "memory")
#define MBAR_EXPECT_TX(a, b) \
    asm volatile("mbarrier.arrive.expect_tx.shared.b64 _, [%0], %1;" :: "r"(a), "r"(b) : "memory")
#define MBAR_WAIT(a, ph) do {                                                            \
    uint32_t _m = (a), _p = (ph), _d;                                                    \
    asm volatile("{ .reg .pred p; mbarrier.try_wait.parity.acquire.cta.shared::cta.b64 " \
                 "p, [%1], %2; selp.b32 %0, 1, 0, p; }"                                  \
                 : "=r"(_d) : "r"(_m), "r"(_p) : "memory");                              \
    if (!_d) {                                                                           \
        asm volatile("{ .reg .pred P1; WL_%=: mbarrier.try_wait.parity.acquire.cta."     \
                     "shared::cta.b64 P1, [%0], %1, 0x989680; @P1 bra.uni WD_%=; "       \
                     "bra.uni WL_%=; WD_%=: }" :: "r"(_m), "r"(_p) : "memory");          \
    }                                                                                    \
} while (0)
#define BULK_G2S(dst, src, sz, mbar) \
    asm volatile("cp.async.bulk.shared::cluster.global.mbarrier::complete_tx::bytes " \
                 "[%0], [%1], %2, [%3];" :: "r"(dst), "l"(src), "r"(sz), "r"(mbar) : "memory")
#define LDSM_X4(r0, r1, r2, r3, addr) \
    asm volatile("ldmatrix.sync.aligned.m8n8.x4.shared.b16 {%0,%1,%2,%3}, [%4];" \
        : "=r"(r0), "=r"(r1), "=r"(r2), "=r"(r3) : "r"(addr))

__device__ __forceinline__ void mma_bf16(float* d, const uint32_t* a, uint32_t b0, uint32_t b1) {
    asm volatile("mma.sync.aligned.m16n8k16.row.col.f32.bf16.bf16.f32 "
        "{%0,%1,%2,%3}, {%4,%5,%6,%7}, {%8,%9}, {%0,%1,%2,%3};"
        : "+f"(d[0]), "+f"(d[1]), "+f"(d[2]), "+f"(d[3])
        : "r"(a[0]), "r"(a[1]), "r"(a[2]), "r"(a[3]), "r"(b0), "r"(b1));
}
__device__ __forceinline__ uint32_t packbf(float a, float b) {  // a->lo, b->hi
    uint32_t r;
    asm("cvt.rn.bf16x2.f32 %0, %1, %2;" : "=r"(r) : "f"(b), "f"(a));
    return r;
}
__device__ __forceinline__ float bf16r(float v) {
    return __bfloat162float(__float2bfloat16(v));
}

// split 32 fp32 -> hi/lo bf16 rows (64B each), store swizzled
__device__ __forceinline__ void store_split64(char* bh, char* bl, uint32_t off0,
                                              uint32_t swm, const float* v) {
    uint32_t hi[16], lo[16];
#pragma unroll
    for (int j = 0; j < 16; j++) {
        float a = v[2 * j], b = v[2 * j + 1];
        hi[j] = packbf(a, b);
        lo[j] = packbf(a - bf16r(a), b - bf16r(b));
    }
#pragma unroll
    for (int g = 0; g < 4; g++) {
        uint32_t o = (off0 + g * 16) ^ swm;
        *(uint4*)(bh + o) = make_uint4(hi[4 * g], hi[4 * g + 1], hi[4 * g + 2], hi[4 * g + 3]);
        *(uint4*)(bl + o) = make_uint4(lo[4 * g], lo[4 * g + 1], lo[4 * g + 2], lo[4 * g + 3]);
    }
}

// ---------------- router + sort ----------------
__global__ void zero_counts_kernel() {
    if (threadIdx.x < E_NUM) d_counts[threadIdx.x] = 0;
}
__global__ void router_kernel(const float* __restrict__ logits) {
    int t = blockIdx.x * blockDim.x + threadIdx.x;
    if (t >= T_TOK) return;
    float l[E_NUM];
#pragma unroll
    for (int e = 0; e < E_NUM; e++) l[e] = logits[t * E_NUM + e];
    int i0 = 0;
#pragma unroll
    for (int e = 1; e < E_NUM; e++) if (l[e] > l[i0]) i0 = e;
    int i1 = (i0 == 0) ? 1 : 0;
#pragma unroll
    for (int e = 0; e < E_NUM; e++) {
        if (e == i0 || e == i1) continue;
        if (l[e] > l[i1]) i1 = e;
    }
    float w0 = 1.f / (1.f + expf(l[i1] - l[i0]));
    d_expert_of_slot[2 * t] = i0; d_expert_of_slot[2 * t + 1] = i1;
    d_w_of_slot[2 * t] = w0;      d_w_of_slot[2 * t + 1] = 1.f - w0;
    atomicAdd(&d_counts[i0], 1);
    atomicAdd(&d_counts[i1], 1);
}
__global__ void setup_kernel() {
    __shared__ int s_off[E_NUM];
    __shared__ int s_cur[E_NUM];
    if (threadIdx.x < MAX_TILES) d_tile_flags[threadIdx.x] = 0;
    if (threadIdx.x == 0) {
        int acc = 0, nt = 0;
        for (int e = 0; e < E_NUM; e++) {
            int c = d_counts[e];
            s_off[e] = acc;
            for (int r = 0; r < c; r += BM) {
                d_tile_expert[nt] = e;
                d_tile_row0[nt] = acc + r;
                d_tile_rowend[nt] = acc + c;
                nt++;
            }
            acc += c;
        }
        d_num_tiles = nt;
    }
    if (threadIdx.x < E_NUM) s_cur[threadIdx.x] = 0;
    __syncthreads();
    for (int s = threadIdx.x; s < S_SLOTS; s += blockDim.x) {
        int e = d_expert_of_slot[s];
        int pos = s_off[e] + atomicAdd(&s_cur[e], 1);
        d_perm[pos] = s;
    }
}

// ---------------- merged prepass: gather_a + conv_w + zero_out in ONE launch ----
#define G_A_BLKS (NCHUNK * MAX_TILES)        // 2304
#define G_W_BLKS (24 * NCHUNK * E_NUM)       // 6144
#define G_Z_BLKS 2048
#define G_TOTAL  (G_A_BLKS + G_W_BLKS + G_Z_BLKS)   // 10496

__global__ void __launch_bounds__(128) prepass_kernel(const float* __restrict__ x,
                                                      const float* __restrict__ up_w,
                                                      const float* __restrict__ dn_w,
                                                      float* __restrict__ out) {
    const int b = blockIdx.x, tid = threadIdx.x;
    if (b < G_A_BLKS) {
        int tile = b >> 5;
        if (tile >= d_num_tiles) return;
        int c = b & 31;
        int r = tid;
        int row0 = d_tile_row0[tile], rowend = d_tile_rowend[tile];
        size_t blk = ((size_t)tile * NCHUNK + c) * BLK_B;
        char* bh = (char*)d_ag_h + blk;
        char* bl = (char*)d_ag_l + blk;
        uint32_t off0 = r * 64, swm = ((r >> 1) & 7) << 4;
        if (row0 + r < rowend) {
            int token = d_perm[row0 + r] >> 1;
            const float4* src = (const float4*)(x + (size_t)token * H_DIM + c * 32);
            float v[32];
#pragma unroll
            for (int j = 0; j < 8; j++) {
                float4 q = src[j];
                v[4 * j] = q.x; v[4 * j + 1] = q.y; v[4 * j + 2] = q.z; v[4 * j + 3] = q.w;
            }
            store_split64(bh, bl, off0, swm, v);
        } else {
            uint4 z = make_uint4(0, 0, 0, 0);
#pragma unroll
            for (int g = 0; g < 4; g++) {
                uint32_t o = (off0 + g * 16) ^ swm;
                *(uint4*)(bh + o) = z;
                *(uint4*)(bl + o) = z;
            }
        }
    } else if (b < G_A_BLKS + G_W_BLKS) {
        int rem = b - G_A_BLKS;
        int e = rem / (24 * NCHUNK);
        int r2 = rem % (24 * NCHUNK);
        int c = r2 / 24;
        int bx = r2 % 24;
        int r = tid;
        const float* src;
        char *bh, *bl;
        int N, ncol;
        if (bx < 16) {
            N = 2 * I_DIM;
            src = up_w + (size_t)e * H_DIM * N;
            int u = bx * 64 + (r >> 1);
            ncol = (r & 1) ? I_DIM + u : u;
            size_t blk = (((size_t)e * 16 + bx) * NCHUNK + c) * BLK_B;
            bh = (char*)d_upwB_h + blk; bl = (char*)d_upwB_l + blk;
        } else {
            N = H_DIM;
            src = dn_w + (size_t)e * I_DIM * N;
            ncol = (bx - 16) * 128 + r;
            size_t blk = (((size_t)e * 8 + (bx - 16)) * NCHUNK + c) * BLK_B;
            bh = (char*)d_dnwB_h + blk; bl = (char*)d_dnwB_l + blk;
        }
        float v[32];
#pragma unroll
        for (int j = 0; j < 32; j++) v[j] = src[(size_t)(c * 32 + j) * N + ncol];
        store_split64(bh, bl, r * 64, ((r >> 1) & 7) << 4, v);
    } else {
        size_t i0 = ((size_t)(b - G_A_BLKS - G_W_BLKS) * 128 + tid) * 4;
        float4* o = (float4*)out;
        float4 z = make_float4(0.f, 0.f, 0.f, 0.f);
#pragma unroll
        for (int j = 0; j < 4; j++) o[i0 + j] = z;
    }
}

// ---------------- fused GEMM1+GEMM2: flag handoff; PROVEN syncthreads mainloop --
// blocks [0,1152): GEMM1 (tile=b>>4, nb=b&15). blocks [1152,1728): GEMM2.
// In-order CTA dispatch => all GEMM1 blocks dispatched before any GEMM2 block
// runs => flag spin cannot deadlock.
#define STAGE_B 32768
#define MB_OFF  (3 * STAGE_B)
#define SMEM_B  (MB_OFF + 64)
#define G1_BLKS (16 * MAX_TILES)   // 1152
#define G2_BLKS (8 * MAX_TILES)    // 576

__global__ void __launch_bounds__(128, 2) gemm_fused_kernel(float* __restrict__ out) {
    const int b = blockIdx.x;
    const int G  = (b < G1_BLKS) ? 1 : 2;
    const int nb = (G == 1) ? (b & 15) : ((b - G1_BLKS) & 7);
    const int tile = (G == 1) ? (b >> 4) : ((b - G1_BLKS) >> 3);
    if (tile >= d_num_tiles) return;
    const int e = d_tile_expert[tile];
    const int row0 = d_tile_row0[tile];
    const int rowend = d_tile_rowend[tile];

    extern __shared__ char smem[];
    const uint32_t sb = smem_u32(smem);
    const int tid = threadIdx.x, wid = tid >> 5, lane = tid & 31;

    const char* Ah = (const char*)((G == 1) ? d_ag_h : d_hbuf_h) + (size_t)tile * NCHUNK * BLK_B;
    const char* Al = (const char*)((G == 1) ? d_ag_l : d_hbuf_l) + (size_t)tile * NCHUNK * BLK_B;
    const char* Bh;
    const char* Bl;
    if (G == 1) {
        size_t wb = ((size_t)e * 16 + nb) * NCHUNK * BLK_B;
        Bh = (const char*)d_upwB_h + wb; Bl = (const char*)d_upwB_l + wb;
    } else {
        size_t wb = ((size_t)e * 8 + nb) * NCHUNK * BLK_B;
        Bh = (const char*)d_dnwB_h + wb; Bl = (const char*)d_dnwB_l + wb;
    }

    if (tid == 0) {
#pragma unroll
        for (int s = 0; s < 3; s++) MBAR_INIT(sb + MB_OFF + s * 8, 1);
    }
    __syncthreads();

    auto fill = [&](int s, int c) {
        uint32_t mb = sb + MB_OFF + s * 8;
        uint32_t st = sb + s * STAGE_B;
        MBAR_EXPECT_TX(mb, (uint32_t)STAGE_B);
        BULK_G2S(st,          Ah + (size_t)c * BLK_B, (uint32_t)BLK_B, mb);
        BULK_G2S(st + 8192,   Al + (size_t)c * BLK_B, (uint32_t)BLK_B, mb);
        BULK_G2S(st + 16384,  Bh + (size_t)c * BLK_B, (uint32_t)BLK_B, mb);
        BULK_G2S(st + 24576,  Bl + (size_t)c * BLK_B, (uint32_t)BLK_B, mb);
    };
    if (tid == 0) {
        if (G == 2) {   // wait for this tile's 16 GEMM1 blocks before reading hbuf
            while (atomicAdd(&d_tile_flags[tile], 0) < 16) __nanosleep(256);
            __threadfence();
        }
        fill(0, 0); fill(1, 1); fill(2, 2);
    }

    // ---- warp tiling: 2 m-warps x 2 n-warps; warp tile 64x64 ----
    const int warp_m = wid >> 1, warp_n = wid & 1;
    const int a_row = warp_m * 64 + (lane & 15);
    const uint32_t a_o0 = (uint32_t)(a_row * 64 + (lane >> 4) * 16);
    const uint32_t swm_a = (uint32_t)(((a_row >> 1) & 7) << 4);
    const int b_row = warp_n * 64 + ((lane >> 4) & 1) * 8 + (lane & 7);
    const uint32_t b_o0 = (uint32_t)(b_row * 64 + ((lane >> 3) & 1) * 16);
    const uint32_t swm_b = (uint32_t)(((b_row >> 1) & 7) << 4);

    float acc[4][8][4];
#pragma unroll
    for (int mt = 0; mt < 4; mt++)
#pragma unroll
        for (int nt = 0; nt < 8; nt++)
#pragma unroll
            for (int q = 0; q < 4; q++) acc[mt][nt][q] = 0.f;

    // ---- PROVEN round-9 mainloop: full-wait, compute, syncthreads, refill ----
    for (int c = 0; c < NCHUNK; c++) {
        const int s = c % 3;
        MBAR_WAIT(sb + MB_OFF + s * 8, (c / 3) & 1);
        const uint32_t st = sb + s * STAGE_B;
#pragma unroll
        for (int kb = 0; kb < 64; kb += 32) {
            uint32_t ah[4][4], al[4][4], bh[4][4], bl[4][4];
#pragma unroll
            for (int mt = 0; mt < 4; mt++) {
                uint32_t ao = (a_o0 + mt * 1024 + kb) ^ swm_a;
                LDSM_X4(ah[mt][0], ah[mt][1], ah[mt][2], ah[mt][3], st + ao);
                LDSM_X4(al[mt][0], al[mt][1], al[mt][2], al[mt][3], st + 8192 + ao);
            }
#pragma unroll
            for (int bp = 0; bp < 4; bp++) {
                uint32_t bo = (b_o0 + bp * 1024 + kb) ^ swm_b;
                LDSM_X4(bh[bp][0], bh[bp][1], bh[bp][2], bh[bp][3], st + 16384 + bo);
                LDSM_X4(bl[bp][0], bl[bp][1], bl[bp][2], bl[bp][3], st + 24576 + bo);
            }
#pragma unroll
            for (int mt = 0; mt < 4; mt++)
#pragma unroll
                for (int nt = 0; nt < 8; nt++)
                    mma_bf16(acc[mt][nt], ah[mt],
                             bh[nt >> 1][(nt & 1) * 2], bh[nt >> 1][(nt & 1) * 2 + 1]);
#pragma unroll
            for (int mt = 0; mt < 4; mt++)
#pragma unroll
                for (int nt = 0; nt < 8; nt++)
                    mma_bf16(acc[mt][nt], al[mt],
                             bh[nt >> 1][(nt & 1) * 2], bh[nt >> 1][(nt & 1) * 2 + 1]);
#pragma unroll
            for (int mt = 0; mt < 4; mt++)
#pragma unroll
                for (int nt = 0; nt < 8; nt++)
                    mma_bf16(acc[mt][nt], ah[mt],
                             bl[nt >> 1][(nt & 1) * 2], bl[nt >> 1][(nt & 1) * 2 + 1]);
        }
        __syncthreads();
        if (c + 3 < NCHUNK && tid == 0) fill(s, c + 3);
    }

    // ---- epilogue ----
    if (G == 1) {
        char* hb = (char*)d_hbuf_h + (size_t)tile * NCHUNK * BLK_B;
        char* lb = (char*)d_hbuf_l + (size_t)tile * NCHUNK * BLK_B;
#pragma unroll
        for (int mt = 0; mt < 4; mt++) {
            int rA = warp_m * 64 + mt * 16 + (lane >> 2);   // local row
            int rB = rA + 8;
#pragma unroll
            for (int nt = 0; nt < 8; nt++) {
                int hc = nb * 64 + warp_n * 32 + nt * 4 + (lane & 3);   // unit col
                size_t blk = (size_t)(hc >> 5) * BLK_B;
                int coff = (hc & 31) * 2;
                float* d = acc[mt][nt];
                {
                    float g = d[0], u = d[1];
                    float h = g / (1.f + expf(-g)) * u;
                    uint32_t o = (uint32_t)(rA * 64 + coff) ^ (uint32_t)(((rA >> 1) & 7) << 4);
                    *(__nv_bfloat16*)(hb + blk + o) = __float2bfloat16(h);
                    *(__nv_bfloat16*)(lb + blk + o) = __float2bfloat16(h - bf16r(h));
                }
                {
                    float g = d[2], u = d[3];
                    float h = g / (1.f + expf(-g)) * u;
                    uint32_t o = (uint32_t)(rB * 64 + coff) ^ (uint32_t)(((rB >> 1) & 7) << 4);
                    *(__nv_bfloat16*)(hb + blk + o) = __float2bfloat16(h);
                    *(__nv_bfloat16*)(lb + blk + o) = __float2bfloat16(h - bf16r(h));
                }
            }
        }
        // publish: all warps' hbuf writes device-visible, then count this block
        __threadfence();
        __syncthreads();
        if (tid == 0) atomicAdd(&d_tile_flags[tile], 1);
    } else {
        // scatter w*acc directly into out; exactly 2 commutative adds/element
#pragma unroll
        for (int mt = 0; mt < 4; mt++) {
            int rA = row0 + warp_m * 64 + mt * 16 + (lane >> 2);
            int rB = rA + 8;
            if (rA < rowend) {
                int slot = d_perm[rA];
                float w = d_w_of_slot[slot];
                float* po = out + (size_t)(slot >> 1) * H_DIM + nb * 128 + warp_n * 64 + 2 * (lane & 3);
#pragma unroll
                for (int nt = 0; nt < 8; nt++) {
                    float* d = acc[mt][nt];
                    atomicAdd(po + nt * 8,     w * d[0]);
                    atomicAdd(po + nt * 8 + 1, w * d[1]);
                }
            }
            if (rB < rowend) {
                int slot = d_perm[rB];
                float w = d_w_of_slot[slot];
                float* po = out + (size_t)(slot >> 1) * H_DIM + nb * 128 + warp_n * 64 + 2 * (lane & 3);
#pragma unroll
                for (int nt = 0; nt < 8; nt++) {
                    float* d = acc[mt][nt];
                    atomicAdd(po + nt * 8,     w * d[2]);
                    atomicAdd(po + nt * 8 + 1, w * d[3]);
                }
            }
        }
    }
}

// ---------------- launch ----------------
extern "C" void kernel_launch(void* const* d_in, const int* in_sizes, int n_in,
                              void* d_out, int out_size) {
    (void)in_sizes; (void)n_in; (void)out_size;
    const float* x      = (const float*)d_in[0];
    const float* logits = (const float*)d_in[1];
    const float* up_w   = (const float*)d_in[2];
    const float* down_w = (const float*)d_in[3];
    float* out = (float*)d_out;

    cudaFuncSetAttribute(gemm_fused_kernel, cudaFuncAttributeMaxDynamicSharedMemorySize, SMEM_B);

    zero_counts_kernel<<<1, 32>>>();                                         // 0
    router_kernel<<<T_TOK / 256, 256>>>(logits);                             // 1
    setup_kernel<<<1, 256>>>();                                              // 2 (zeroes flags)
    prepass_kernel<<<G_TOTAL, 128>>>(x, up_w, down_w, out);                  // 3
    gemm_fused_kernel<<<G1_BLKS + G2_BLKS, 128, SMEM_B>>>(out);              // 4 (fused)
}